// round 10
// baseline (speedup 1.0000x reference)
#include <cuda_runtime.h>

#define NN     50000
#define HD_    128
#define EMAX   800000
#define ETMAX  (EMAX + NN)
#define NGRP   64
#define OUTC   64

// ---------------- scratch ----------------
__device__ float  g_h[NN * HD_];
__device__ float  g_agg[NN * HD_];
__device__ float  g_als[NN * 4];
__device__ float  g_ald[NN * 4];
__device__ int    g_deg[NN];
__device__ int    g_roff[NN + 1];
__device__ int    g_cur[NN];
__device__ int    g_csrc[ETMAX];
__device__ float  g_bn[4 * HD_];   // sum | sumsq | scale | shift
__device__ float  g_pool[NGRP * OUTC];
__device__ float  g_cnt[NGRP];
__device__ float  g_wpack[4 * 32768];  // per-layer fragment-packed W (hi/lo tf32)

static inline int ceil_div(int a, int b) { return (a + b - 1) / b; }

__device__ __forceinline__ float lrelu(float v) { return v > 0.f ? v : 0.2f * v; }
__device__ __forceinline__ float elu_f(float y) { return y > 0.f ? y : __expf(y) - 1.f; }

__device__ __forceinline__ void tf32split(float x, unsigned& hi, unsigned& lo) {
    asm("cvt.rna.tf32.f32 %0, %1;" : "=r"(hi) : "f"(x));
    float r = x - __uint_as_float(hi);
    asm("cvt.rna.tf32.f32 %0, %1;" : "=r"(lo) : "f"(r));
}

#define MMA_TF32(d, a0, a1, a2, a3, b0, b1)                                   \
    asm volatile("mma.sync.aligned.m16n8k8.row.col.f32.tf32.tf32.f32 "        \
                 "{%0,%1,%2,%3}, {%4,%5,%6,%7}, {%8,%9}, {%0,%1,%2,%3};"      \
                 : "+f"(d[0]), "+f"(d[1]), "+f"(d[2]), "+f"(d[3])             \
                 : "r"(a0), "r"(a1), "r"(a2), "r"(a3), "r"(b0), "r"(b1))

// ---------------- misc ----------------
__global__ void clear_i(int* p, int n) {
    for (int i = blockIdx.x * blockDim.x + threadIdx.x; i < n; i += gridDim.x * blockDim.x)
        p[i] = 0;
}

// ---------------- W fragment packing (hi/lo tf32, mma thread order) ---------
// out float4 index: (k8*NT8 + n8)*32 + lane  ->  {b0hi, b1hi, b0lo, b1lo}
__global__ void wpack_k(const float* __restrict__ W, float* __restrict__ out, int M) {
    int k8 = blockIdx.x, n8 = blockIdx.y, lane = threadIdx.x;
    int kk = k8 * 8 + (lane & 3);
    int nn = n8 * 8 + (lane >> 2);
    float b0 = __ldg(&W[kk * M + nn]);
    float b1 = __ldg(&W[(kk + 4) * M + nn]);
    unsigned h0, l0, h1, l1;
    tf32split(b0, h0, l0);
    tf32split(b1, h1, l1);
    float4 v = make_float4(__uint_as_float(h0), __uint_as_float(h1),
                           __uint_as_float(l0), __uint_as_float(l1));
    ((float4*)out)[(k8 * gridDim.y + n8) * 32 + lane] = v;
}

// ---------------- CSR build ----------------
__global__ void hist_k(const int* __restrict__ ei, int* __restrict__ deg, int E, int ET) {
    for (int e = blockIdx.x * blockDim.x + threadIdx.x; e < ET; e += gridDim.x * blockDim.x) {
        int d = (e < E) ? __ldg(&ei[E + e]) : (e - E);
        atomicAdd(&deg[d], 1);
    }
}

__global__ void scan_k(const int* __restrict__ deg, int* __restrict__ roff,
                       int* __restrict__ cur) {
    __shared__ int ssum[1024];
    int tid = threadIdx.x;
    const int CH = (NN + 1023) / 1024;
    int base = tid * CH;
    int s = 0;
    for (int i = 0; i < CH; i++) {
        int n = base + i;
        if (n < NN) s += deg[n];
    }
    ssum[tid] = s;
    __syncthreads();
    for (int off = 1; off < 1024; off <<= 1) {
        int v = 0;
        if (tid >= off) v = ssum[tid - off];
        __syncthreads();
        if (tid >= off) ssum[tid] += v;
        __syncthreads();
    }
    int run = (tid == 0) ? 0 : ssum[tid - 1];
    for (int i = 0; i < CH; i++) {
        int n = base + i;
        if (n < NN) {
            roff[n] = run;
            cur[n]  = run;
            run += deg[n];
        }
    }
    if (tid == 1023) roff[NN] = ssum[1023];
}

__global__ void scatter_k(const int* __restrict__ ei, int* __restrict__ cur,
                          int* __restrict__ csrc, int E, int ET) {
    for (int e = blockIdx.x * blockDim.x + threadIdx.x; e < ET; e += gridDim.x * blockDim.x) {
        int s, d;
        if (e < E) { s = __ldg(&ei[e]); d = __ldg(&ei[E + e]); }
        else       { s = d = e - E; }
        int pos = atomicAdd(&cur[d], 1);
        csrc[pos] = s;
    }
}

// ---------------- GEMM (3xTF32 mma.sync) + fused attention logits -----------
// C[rows, M] = act(A)[rows,128] @ W[128,M].  Block = 128 threads (4 warps),
// 64 rows per block (16 per warp).  W pre-packed per-fragment in wpack.
template <int M, bool BNIN, int H, int C>
__global__ void gemm_attn_k(const float* __restrict__ A, const float* __restrict__ wpack,
                            const float* __restrict__ bn,
                            const float* __restrict__ a_s, const float* __restrict__ a_d,
                            float* __restrict__ Cout, float* __restrict__ als,
                            float* __restrict__ ald, int rows) {
    const int NT8 = M / 8;
    const int LD  = M + 4;
    __shared__ float sm[64 * (M + 4)];

    int t = threadIdx.x;
    int w = t >> 5, lane = t & 31;
    int row0 = blockIdx.x * 64;
    int g  = lane >> 2;        // groupID
    int c0 = lane & 3;         // threadID_in_group
    int rA = row0 + w * 16 + g;
    int rB = rA + 8;
    bool okA = rA < rows, okB = rB < rows;
    const float* pA = A + (size_t)rA * 128 + c0;
    const float* pB = A + (size_t)rB * 128 + c0;

    float d[NT8][4];
#pragma unroll
    for (int n8 = 0; n8 < NT8; n8++)
#pragma unroll
        for (int i = 0; i < 4; i++) d[n8][i] = 0.f;

    for (int k8 = 0; k8 < 16; k8++) {
        int k0 = k8 * 8;
        float a0 = okA ? __ldg(pA + k0)     : 0.f;
        float a2 = okA ? __ldg(pA + k0 + 4) : 0.f;
        float a1 = okB ? __ldg(pB + k0)     : 0.f;
        float a3 = okB ? __ldg(pB + k0 + 4) : 0.f;
        if (BNIN) {
            float sc0 = __ldg(&bn[2 * HD_ + k0 + c0]);
            float sh0 = __ldg(&bn[3 * HD_ + k0 + c0]);
            float sc4 = __ldg(&bn[2 * HD_ + k0 + c0 + 4]);
            float sh4 = __ldg(&bn[3 * HD_ + k0 + c0 + 4]);
            a0 = elu_f(a0 * sc0 + sh0);
            a1 = elu_f(a1 * sc0 + sh0);
            a2 = elu_f(a2 * sc4 + sh4);
            a3 = elu_f(a3 * sc4 + sh4);
        }
        unsigned ah0, ah1, ah2, ah3, al0, al1, al2, al3;
        tf32split(a0, ah0, al0);
        tf32split(a1, ah1, al1);
        tf32split(a2, ah2, al2);
        tf32split(a3, ah3, al3);

        const float4* wp = (const float4*)wpack + (size_t)(k8 * NT8) * 32 + lane;
#pragma unroll
        for (int n8 = 0; n8 < NT8; n8++) {
            float4 b = __ldg(&wp[n8 * 32]);
            unsigned bh0 = __float_as_uint(b.x), bh1 = __float_as_uint(b.y);
            unsigned bl0 = __float_as_uint(b.z), bl1 = __float_as_uint(b.w);
            MMA_TF32(d[n8], ah0, ah1, ah2, ah3, bl0, bl1);  // hi*lo
            MMA_TF32(d[n8], al0, al1, al2, al3, bh0, bh1);  // lo*hi
            MMA_TF32(d[n8], ah0, ah1, ah2, ah3, bh0, bh1);  // hi*hi
        }
    }

    // stage D tile to smem (fragment layout -> row-major)
    int rloc = w * 16 + g;
#pragma unroll
    for (int n8 = 0; n8 < NT8; n8++) {
        int col = n8 * 8 + c0 * 2;
        *(float2*)&sm[rloc * LD + col]       = make_float2(d[n8][0], d[n8][1]);
        *(float2*)&sm[(rloc + 8) * LD + col] = make_float2(d[n8][2], d[n8][3]);
    }
    __syncthreads();

    // coalesced C store from smem
    for (int i = t; i < 64 * (M / 4); i += 128) {
        int r = i / (M / 4), c4 = i % (M / 4);
        int gr = row0 + r;
        if (gr < rows)
            *(float4*)&Cout[(size_t)gr * M + c4 * 4] = *(float4*)&sm[r * LD + c4 * 4];
    }

    // attention logits from the smem tile
    if (H == 4) {
        for (int task = t; task < 256; task += 128) {
            int row = task & 63, head = task >> 6;
            const float4* hrow = (const float4*)&sm[row * LD + head * C];
            const float4* ap = (const float4*)(a_s + head * C);
            const float4* dp = (const float4*)(a_d + head * C);
            float s1 = 0.f, s2 = 0.f;
#pragma unroll
            for (int c4 = 0; c4 < C / 4; c4++) {
                float4 v = hrow[c4];
                float4 a = __ldg(&ap[c4]);
                float4 dd = __ldg(&dp[c4]);
                s1 += v.x * a.x + v.y * a.y + v.z * a.z + v.w * a.w;
                s2 += v.x * dd.x + v.y * dd.y + v.z * dd.z + v.w * dd.w;
            }
            int gr = row0 + row;
            if (gr < rows) {
                als[gr * 4 + head] = s1;
                ald[gr * 4 + head] = s2;
            }
        }
    } else {
        int row = t & 63, sel = t >> 6;
        const float4* av = (const float4*)(sel ? a_d : a_s);
        const float4* hrow = (const float4*)&sm[row * LD];
        float acc1 = 0.f;
#pragma unroll
        for (int c4 = 0; c4 < C / 4; c4++) {
            float4 v = hrow[c4];
            float4 a = __ldg(&av[c4]);
            acc1 += v.x * a.x + v.y * a.y + v.z * a.z + v.w * a.w;
        }
        int gr = row0 + row;
        if (gr < rows) {
            if (sel) ald[gr] = acc1; else als[gr] = acc1;
        }
    }
}

// ---------------- fused per-node GAT aggregation (warp per node) ------------
template <int H, int M, bool STATS>
__global__ void aggregate_k(const int* __restrict__ roff, const int* __restrict__ csrc,
                            const float* __restrict__ h, const float* __restrict__ als,
                            const float* __restrict__ ald, const float* __restrict__ bias,
                            float* __restrict__ out, float* __restrict__ bn) {
    __shared__ float sred[2 * HD_];
    __shared__ float4 sE[8 * 32];
    __shared__ int    sS[8 * 32];
    int t = threadIdx.x;
    if (STATS) {
        if (t < 2 * HD_) sred[t] = 0.f;
        __syncthreads();
    }
    int node = (blockIdx.x * blockDim.x + t) >> 5;
    int lane = t & 31;
    int w = t >> 5;
    bool active = (node < NN);
    int beg = 0, end = 0;
    if (active) { beg = roff[node]; end = roff[node + 1]; }

    float ad0 = 0.f, ad1 = 0.f, ad2 = 0.f, ad3 = 0.f;
    if (active) {
        if (H == 4) {
            float4 tt = *(const float4*)&ald[node * 4];
            ad0 = tt.x; ad1 = tt.y; ad2 = tt.z; ad3 = tt.w;
        } else {
            ad0 = ald[node];
        }
    }

    int jj = beg + lane;
    bool have = active && (jj < end);
    int sreg = 0;
    float s0 = 0.f, s1 = 0.f, s2 = 0.f, s3 = 0.f;
    if (have) {
        sreg = csrc[jj];
        float4 e;
        if (H == 4) {
            float4 a = *(const float4*)&als[sreg * 4];
            e.x = __expf(lrelu(a.x + ad0));
            e.y = __expf(lrelu(a.y + ad1));
            e.z = __expf(lrelu(a.z + ad2));
            e.w = __expf(lrelu(a.w + ad3));
            s0 += e.x; s1 += e.y; s2 += e.z; s3 += e.w;
        } else {
            e.x = __expf(lrelu(als[sreg] + ad0));
            e.y = e.z = e.w = 0.f;
            s0 += e.x;
        }
        sE[w * 32 + lane] = e;
        sS[w * 32 + lane] = sreg;
    }
    for (int j = jj + 32; j < end; j += 32) {
        int s = csrc[j];
        if (H == 4) {
            float4 a = *(const float4*)&als[s * 4];
            s0 += __expf(lrelu(a.x + ad0));
            s1 += __expf(lrelu(a.y + ad1));
            s2 += __expf(lrelu(a.z + ad2));
            s3 += __expf(lrelu(a.w + ad3));
        } else {
            s0 += __expf(lrelu(als[s] + ad0));
        }
    }
#pragma unroll
    for (int o = 16; o; o >>= 1) {
        s0 += __shfl_xor_sync(0xffffffffu, s0, o);
        if (H == 4) {
            s1 += __shfl_xor_sync(0xffffffffu, s1, o);
            s2 += __shfl_xor_sync(0xffffffffu, s2, o);
            s3 += __shfl_xor_sync(0xffffffffu, s3, o);
        }
    }
    __syncwarp();

    int cnt = end - beg;
    int cached = cnt < 32 ? cnt : 32;

    if (H == 4) {
        float r0 = 1.f / (s0 + 1e-16f), r1 = 1.f / (s1 + 1e-16f);
        float r2 = 1.f / (s2 + 1e-16f), r3 = 1.f / (s3 + 1e-16f);
        int head = lane >> 3;
        float rv  = lane < 16 ? (lane < 8 ? r0 : r1) : (lane < 24 ? r2 : r3);
        float adh = lane < 16 ? (lane < 8 ? ad0 : ad1) : (lane < 24 ? ad2 : ad3);

        float4 acc = make_float4(0.f, 0.f, 0.f, 0.f);
        const float* eb = (const float*)&sE[w * 32];
        const int*   sb = &sS[w * 32];
        int j2 = 0;
        for (; j2 + 4 <= cached; j2 += 4) {
            int sA = sb[j2], sB = sb[j2 + 1], sC = sb[j2 + 2], sD = sb[j2 + 3];
            float evA = eb[(j2 + 0) * 4 + head];
            float evB = eb[(j2 + 1) * 4 + head];
            float evC = eb[(j2 + 2) * 4 + head];
            float evD = eb[(j2 + 3) * 4 + head];
            float4 hA = *(const float4*)&h[(size_t)sA * 128 + lane * 4];
            float4 hB = *(const float4*)&h[(size_t)sB * 128 + lane * 4];
            float4 hC = *(const float4*)&h[(size_t)sC * 128 + lane * 4];
            float4 hD = *(const float4*)&h[(size_t)sD * 128 + lane * 4];
            acc.x += hA.x * evA + hB.x * evB + hC.x * evC + hD.x * evD;
            acc.y += hA.y * evA + hB.y * evB + hC.y * evC + hD.y * evD;
            acc.z += hA.z * evA + hB.z * evB + hC.z * evC + hD.z * evD;
            acc.w += hA.w * evA + hB.w * evB + hC.w * evC + hD.w * evD;
        }
        for (; j2 < cached; j2++) {
            int sA = sb[j2];
            float evA = eb[j2 * 4 + head];
            float4 hA = *(const float4*)&h[(size_t)sA * 128 + lane * 4];
            acc.x += hA.x * evA; acc.y += hA.y * evA;
            acc.z += hA.z * evA; acc.w += hA.w * evA;
        }
        for (int j = beg + 32; j < end; j++) {
            int s = csrc[j];
            float4 a = *(const float4*)&als[s * 4];
            float ah = lane < 16 ? (lane < 8 ? a.x : a.y) : (lane < 24 ? a.z : a.w);
            float ev = __expf(lrelu(ah + adh));
            float4 hv = *(const float4*)&h[(size_t)s * 128 + lane * 4];
            acc.x += hv.x * ev; acc.y += hv.y * ev;
            acc.z += hv.z * ev; acc.w += hv.w * ev;
        }
        float4 bi = active ? *(const float4*)&bias[lane * 4]
                           : make_float4(0.f, 0.f, 0.f, 0.f);
        float4 ov;
        ov.x = acc.x * rv + bi.x;
        ov.y = acc.y * rv + bi.y;
        ov.z = acc.z * rv + bi.z;
        ov.w = acc.w * rv + bi.w;
        if (active) *(float4*)&out[(size_t)node * 128 + lane * 4] = ov;

        if (STATS) {
            if (active) {
                int ch = lane * 4;
                atomicAdd(&sred[ch + 0], ov.x);
                atomicAdd(&sred[ch + 1], ov.y);
                atomicAdd(&sred[ch + 2], ov.z);
                atomicAdd(&sred[ch + 3], ov.w);
                atomicAdd(&sred[HD_ + ch + 0], ov.x * ov.x);
                atomicAdd(&sred[HD_ + ch + 1], ov.y * ov.y);
                atomicAdd(&sred[HD_ + ch + 2], ov.z * ov.z);
                atomicAdd(&sred[HD_ + ch + 3], ov.w * ov.w);
            }
            __syncthreads();
            if (t < 2 * HD_) atomicAdd(&bn[t], sred[t]);
        }
    } else {
        float r0 = 1.f / (s0 + 1e-16f);
        float2 acc = make_float2(0.f, 0.f);
        const float* eb = (const float*)&sE[w * 32];
        const int*   sb = &sS[w * 32];
        int j2 = 0;
        for (; j2 + 4 <= cached; j2 += 4) {
            int sA = sb[j2], sB = sb[j2 + 1], sC = sb[j2 + 2], sD = sb[j2 + 3];
            float eA = eb[(j2 + 0) * 4];
            float eB = eb[(j2 + 1) * 4];
            float eC = eb[(j2 + 2) * 4];
            float eD = eb[(j2 + 3) * 4];
            float2 hA = *(const float2*)&h[(size_t)sA * 64 + lane * 2];
            float2 hB = *(const float2*)&h[(size_t)sB * 64 + lane * 2];
            float2 hC = *(const float2*)&h[(size_t)sC * 64 + lane * 2];
            float2 hD = *(const float2*)&h[(size_t)sD * 64 + lane * 2];
            acc.x += hA.x * eA + hB.x * eB + hC.x * eC + hD.x * eD;
            acc.y += hA.y * eA + hB.y * eB + hC.y * eC + hD.y * eD;
        }
        for (; j2 < cached; j2++) {
            int sA = sb[j2];
            float eA = eb[j2 * 4];
            float2 hA = *(const float2*)&h[(size_t)sA * 64 + lane * 2];
            acc.x += hA.x * eA;
            acc.y += hA.y * eA;
        }
        for (int j = beg + 32; j < end; j++) {
            int s = csrc[j];
            float ev = __expf(lrelu(als[s] + ad0));
            float2 hv = *(const float2*)&h[(size_t)s * 64 + lane * 2];
            acc.x += hv.x * ev;
            acc.y += hv.y * ev;
        }
        if (active) {
            float2 bi = *(const float2*)&bias[lane * 2];
            float2 ov;
            ov.x = acc.x * r0 + bi.x;
            ov.y = acc.y * r0 + bi.y;
            *(float2*)&out[(size_t)node * 64 + lane * 2] = ov;
        }
    }
}

// ---------------- BN finalize (self-clearing; optionally clears pool) -------
__global__ void bn_finalize(float* __restrict__ bn, const float* __restrict__ g,
                            const float* __restrict__ be, float* __restrict__ pool,
                            float* __restrict__ cnt, int clearPool) {
    int j = threadIdx.x;
    float mu = bn[j] / (float)NN;
    float var = bn[HD_ + j] / (float)NN - mu * mu;
    float sc = __ldg(&g[j]) * rsqrtf(var + 1e-5f);
    bn[2 * HD_ + j] = sc;
    bn[3 * HD_ + j] = __ldg(&be[j]) - mu * sc;
    bn[j] = 0.f;
    bn[HD_ + j] = 0.f;
    if (clearPool) {
        for (int i = j; i < NGRP * OUTC; i += HD_) pool[i] = 0.f;
        if (j < NGRP) cnt[j] = 0.f;
    }
}

// ---------------- global mean pool ----------------
__global__ void pool_acc(const float* __restrict__ v, const int* __restrict__ bid,
                         float* __restrict__ pool, float* __restrict__ cnt) {
    int idx = blockIdx.x * blockDim.x + threadIdx.x;
    if (idx >= NN * OUTC) return;
    int n = idx >> 6, j = idx & 63;
    int g = __ldg(&bid[n]);
    atomicAdd(&pool[g * OUTC + j], v[(size_t)n * OUTC + j]);
    if (j == 0) atomicAdd(&cnt[g], 1.f);
}

__global__ void pool_fin(const float* __restrict__ pool, const float* __restrict__ cnt,
                         float* __restrict__ out) {
    int i = blockIdx.x * blockDim.x + threadIdx.x;
    if (i >= NGRP * OUTC) return;
    float c = cnt[i >> 6];
    out[i] = pool[i] / fmaxf(c, 1.f);
}

// ---------------- host ----------------
extern "C" void kernel_launch(void* const* d_in, const int* in_sizes, int n_in,
                              void* d_out, int out_size) {
    const float* x   = (const float*)d_in[0];
    const int*   ei  = (const int*)d_in[1];
    const int*   bid = (const int*)d_in[2];
    const float *W[4], *As[4], *Ad[4], *B[4];
    for (int i = 0; i < 4; i++) {
        W[i]  = (const float*)d_in[3 + 4 * i];
        As[i] = (const float*)d_in[4 + 4 * i];
        Ad[i] = (const float*)d_in[5 + 4 * i];
        B[i]  = (const float*)d_in[6 + 4 * i];
    }
    const float *G[3], *Be[3];
    for (int i = 0; i < 3; i++) {
        G[i]  = (const float*)d_in[19 + 2 * i];
        Be[i] = (const float*)d_in[20 + 2 * i];
    }
    int E  = in_sizes[1] / 2;
    int ET = E + NN;

    float *h_, *agg_, *als_, *ald_, *bn_, *pool_, *cnt_, *wp_;
    int *deg_, *roff_, *cur_, *csrc_;
    cudaGetSymbolAddress((void**)&h_,    g_h);
    cudaGetSymbolAddress((void**)&agg_,  g_agg);
    cudaGetSymbolAddress((void**)&als_,  g_als);
    cudaGetSymbolAddress((void**)&ald_,  g_ald);
    cudaGetSymbolAddress((void**)&deg_,  g_deg);
    cudaGetSymbolAddress((void**)&roff_, g_roff);
    cudaGetSymbolAddress((void**)&cur_,  g_cur);
    cudaGetSymbolAddress((void**)&csrc_, g_csrc);
    cudaGetSymbolAddress((void**)&bn_,   g_bn);
    cudaGetSymbolAddress((void**)&pool_, g_pool);
    cudaGetSymbolAddress((void**)&cnt_,  g_cnt);
    cudaGetSymbolAddress((void**)&wp_,   g_wpack);

    const int TB = 256;
    const int AGG_BLOCKS = ceil_div(NN * 32, TB);
    const int GB = ceil_div(NN, 64);

    // ---- W fragment packing (independent of data; run first) ----
    for (int l = 0; l < 3; l++)
        wpack_k<<<dim3(16, 16), 32>>>(W[l], wp_ + l * 32768, 128);
    wpack_k<<<dim3(16, 8), 32>>>(W[3], wp_ + 3 * 32768, 64);

    // ---- CSR build + layer-0 GEMM overlap ----
    clear_i<<<128, TB>>>(deg_, NN);
    hist_k<<<1024, TB>>>(ei, deg_, E, ET);
    scan_k<<<1, 1024>>>(deg_, roff_, cur_);
    gemm_attn_k<128, false, 4, 32><<<GB, 128>>>(x, wp_, bn_, As[0], Ad[0],
                                                h_, als_, ald_, NN);
    scatter_k<<<1024, TB>>>(ei, cur_, csrc_, E, ET);

    // ---- layer 0 aggregation ----
    aggregate_k<4, 128, true><<<AGG_BLOCKS, TB>>>(roff_, csrc_, h_, als_, ald_, B[0],
                                                  agg_, bn_);
    bn_finalize<<<1, HD_>>>(bn_, G[0], Be[0], pool_, cnt_, 0);

    // ---- layers 1,2 ----
    for (int l = 1; l < 3; l++) {
        gemm_attn_k<128, true, 4, 32><<<GB, 128>>>(agg_, wp_ + l * 32768, bn_,
                                                   As[l], Ad[l], h_, als_, ald_, NN);
        aggregate_k<4, 128, true><<<AGG_BLOCKS, TB>>>(roff_, csrc_, h_, als_, ald_, B[l],
                                                      agg_, bn_);
        bn_finalize<<<1, HD_>>>(bn_, G[l], Be[l], pool_, cnt_, l == 2);
    }

    // ---- layer 3 (H=1, OUT=64) ----
    gemm_attn_k<64, true, 1, 64><<<GB, 128>>>(agg_, wp_ + 3 * 32768, bn_,
                                              As[3], Ad[3], h_, als_, ald_, NN);
    aggregate_k<1, 64, false><<<AGG_BLOCKS, TB>>>(roff_, csrc_, h_, als_, ald_, B[3],
                                                  agg_, bn_);

    // ---- global mean pool ----
    pool_acc<<<ceil_div(NN * OUTC, TB), TB>>>(agg_, bid, pool_, cnt_);
    pool_fin<<<ceil_div(NGRP * OUTC, TB), TB>>>(pool_, cnt_, (float*)d_out);
}

// round 11
// speedup vs baseline: 1.1115x; 1.1115x over previous
#include <cuda_runtime.h>

#define NN     50000
#define HD_    128
#define EMAX   800000
#define ETMAX  (EMAX + NN)
#define NGRP   64
#define OUTC   64

// ---------------- scratch ----------------
__device__ float  g_h[NN * HD_];
__device__ float  g_agg[NN * HD_];
__device__ float  g_als[NN * 4];
__device__ float  g_ald[NN * 4];
__device__ int    g_deg[NN];
__device__ int    g_roff[NN + 1];
__device__ int    g_cur[NN];
__device__ int    g_csrc[ETMAX];
__device__ float  g_bn[4 * HD_];   // sum | sumsq | scale | shift
__device__ float  g_pool[NGRP * OUTC];
__device__ float  g_cnt[NGRP];

static inline int ceil_div(int a, int b) { return (a + b - 1) / b; }

__device__ __forceinline__ float lrelu(float v) { return v > 0.f ? v : 0.2f * v; }
__device__ __forceinline__ float elu_f(float y) { return y > 0.f ? y : __expf(y) - 1.f; }

// ---------------- misc ----------------
__global__ void clear_i(int* p, int n) {
    for (int i = blockIdx.x * blockDim.x + threadIdx.x; i < n; i += gridDim.x * blockDim.x)
        p[i] = 0;
}

// ---------------- CSR build ----------------
__global__ void hist_k(const int* __restrict__ ei, int* __restrict__ deg, int E, int ET) {
    for (int e = blockIdx.x * blockDim.x + threadIdx.x; e < ET; e += gridDim.x * blockDim.x) {
        int d = (e < E) ? __ldg(&ei[E + e]) : (e - E);
        atomicAdd(&deg[d], 1);
    }
}

__global__ void scan_k(const int* __restrict__ deg, int* __restrict__ roff,
                       int* __restrict__ cur) {
    __shared__ int ssum[1024];
    int tid = threadIdx.x;
    const int CH = (NN + 1023) / 1024;
    int base = tid * CH;
    int s = 0;
    for (int i = 0; i < CH; i++) {
        int n = base + i;
        if (n < NN) s += deg[n];
    }
    ssum[tid] = s;
    __syncthreads();
    for (int off = 1; off < 1024; off <<= 1) {
        int v = 0;
        if (tid >= off) v = ssum[tid - off];
        __syncthreads();
        if (tid >= off) ssum[tid] += v;
        __syncthreads();
    }
    int run = (tid == 0) ? 0 : ssum[tid - 1];
    for (int i = 0; i < CH; i++) {
        int n = base + i;
        if (n < NN) {
            roff[n] = run;
            cur[n]  = run;
            run += deg[n];
        }
    }
    if (tid == 1023) roff[NN] = ssum[1023];
}

__global__ void scatter_k(const int* __restrict__ ei, int* __restrict__ cur,
                          int* __restrict__ csrc, int E, int ET) {
    for (int e = blockIdx.x * blockDim.x + threadIdx.x; e < ET; e += gridDim.x * blockDim.x) {
        int s, d;
        if (e < E) { s = __ldg(&ei[e]); d = __ldg(&ei[E + e]); }
        else       { s = d = e - E; }
        int pos = atomicAdd(&cur[d], 1);
        csrc[pos] = s;
    }
}

// ---------------- GEMM (R4-proven core) + fused attention logits ------------
template <int M, bool BNIN, int H, int C>
__global__ __launch_bounds__(128, 7)
void gemm_attn_k(const float* __restrict__ A, const float* __restrict__ W,
                 const float* __restrict__ bn,
                 const float* __restrict__ a_s, const float* __restrict__ a_d,
                 float* __restrict__ Cout, float* __restrict__ als,
                 float* __restrict__ ald, int rows) {
    __shared__ float sm[4224];   // phase A: xs[32][128]; phase B: hs[32][M+4]
    int row0 = blockIdx.x * 32;
    int t = threadIdx.x;
    const int CG = M / 4;
    int cg = t % CG;
    int rg = t / CG;   // 0..3

    for (int i = t; i < 32 * 32; i += M) {
        int r = i >> 5, c4 = i & 31;
        float4 v = make_float4(0.f, 0.f, 0.f, 0.f);
        if (row0 + r < rows) {
            v = *(const float4*)&A[(size_t)(row0 + r) * 128 + c4 * 4];
            if (BNIN) {
                float4 sc = *(const float4*)&bn[2 * HD_ + c4 * 4];
                float4 sh = *(const float4*)&bn[3 * HD_ + c4 * 4];
                v.x = elu_f(v.x * sc.x + sh.x);
                v.y = elu_f(v.y * sc.y + sh.y);
                v.z = elu_f(v.z * sc.z + sh.z);
                v.w = elu_f(v.w * sc.w + sh.w);
            }
        }
        *(float4*)&sm[r * 128 + c4 * 4] = v;
    }
    __syncthreads();

    float acc[8][4];
#pragma unroll
    for (int r = 0; r < 8; r++)
#pragma unroll
        for (int j = 0; j < 4; j++) acc[r][j] = 0.f;

    const float4* xs4 = (const float4*)sm;
#pragma unroll 4
    for (int k4 = 0; k4 < 32; k4++) {
        float4 w0 = __ldg((const float4*)&W[(size_t)(k4 * 4 + 0) * M + cg * 4]);
        float4 w1 = __ldg((const float4*)&W[(size_t)(k4 * 4 + 1) * M + cg * 4]);
        float4 w2 = __ldg((const float4*)&W[(size_t)(k4 * 4 + 2) * M + cg * 4]);
        float4 w3 = __ldg((const float4*)&W[(size_t)(k4 * 4 + 3) * M + cg * 4]);
#pragma unroll
        for (int r = 0; r < 8; r++) {
            float4 xv = xs4[(rg * 8 + r) * 32 + k4];
            acc[r][0] += xv.x * w0.x + xv.y * w1.x + xv.z * w2.x + xv.w * w3.x;
            acc[r][1] += xv.x * w0.y + xv.y * w1.y + xv.z * w2.y + xv.w * w3.y;
            acc[r][2] += xv.x * w0.z + xv.y * w1.z + xv.z * w2.z + xv.w * w3.z;
            acc[r][3] += xv.x * w0.w + xv.y * w1.w + xv.z * w2.w + xv.w * w3.w;
        }
    }
    __syncthreads();   // xs no longer needed; reuse sm as hs[32][M+4]

    const int LD = M + 4;
#pragma unroll
    for (int r = 0; r < 8; r++) {
        int row = rg * 8 + r;
        float4 o = make_float4(acc[r][0], acc[r][1], acc[r][2], acc[r][3]);
        *(float4*)&sm[row * LD + cg * 4] = o;
        if (row0 + row < rows) *(float4*)&Cout[(size_t)(row0 + row) * M + cg * 4] = o;
    }
    __syncthreads();

    if (H == 4) {
        int row = t & 31, head = t >> 5;   // warp-uniform head
        const float4* hrow = (const float4*)&sm[row * LD + head * C];
        const float4* ap = (const float4*)(a_s + head * C);
        const float4* dp = (const float4*)(a_d + head * C);
        float s1 = 0.f, s2 = 0.f;
#pragma unroll
        for (int c4 = 0; c4 < C / 4; c4++) {
            float4 v = hrow[c4];
            float4 a = __ldg(&ap[c4]);
            float4 d = __ldg(&dp[c4]);
            s1 += v.x * a.x + v.y * a.y + v.z * a.z + v.w * a.w;
            s2 += v.x * d.x + v.y * d.y + v.z * d.z + v.w * d.w;
        }
        int gr = row0 + row;
        if (gr < rows) {
            als[gr * 4 + head] = s1;
            ald[gr * 4 + head] = s2;
        }
    } else {
        int row = t & 31, sel = t >> 5;
        const float4* av = (const float4*)(sel ? a_d : a_s);
        const float4* hrow = (const float4*)&sm[row * LD];
        float acc1 = 0.f;
#pragma unroll
        for (int c4 = 0; c4 < C / 4; c4++) {
            float4 v = hrow[c4];
            float4 a = __ldg(&av[c4]);
            acc1 += v.x * a.x + v.y * a.y + v.z * a.z + v.w * a.w;
        }
        int gr = row0 + row;
        if (gr < rows) {
            if (sel) ald[gr] = acc1; else als[gr] = acc1;
        }
    }
}

// ---------------- fused per-node GAT aggregation (warp per node) ------------
// No segment-max pass (softmax shift-invariance; logits O(+-5) are exp-safe).
// H==1 additionally fuses the global mean-pool accumulation (bid sorted).
template <int H, int M, bool STATS, bool POOL>
__global__ void aggregate_k(const int* __restrict__ roff, const int* __restrict__ csrc,
                            const float* __restrict__ h, const float* __restrict__ als,
                            const float* __restrict__ ald, const float* __restrict__ bias,
                            float* __restrict__ out, float* __restrict__ bn,
                            const int* __restrict__ bid, float* __restrict__ pool,
                            float* __restrict__ cnt) {
    __shared__ float sred[2 * HD_];
    __shared__ float4 sE[8 * 32];
    __shared__ int    sS[8 * 32];
    int t = threadIdx.x;
    if (STATS) {
        if (t < 2 * HD_) sred[t] = 0.f;
        __syncthreads();
    }
    int node = (blockIdx.x * blockDim.x + t) >> 5;
    int lane = t & 31;
    int w = t >> 5;
    bool active = (node < NN);
    int beg = 0, end = 0;
    if (active) { beg = roff[node]; end = roff[node + 1]; }

    float ad0 = 0.f, ad1 = 0.f, ad2 = 0.f, ad3 = 0.f;
    if (active) {
        if (H == 4) {
            float4 tt = *(const float4*)&ald[node * 4];
            ad0 = tt.x; ad1 = tt.y; ad2 = tt.z; ad3 = tt.w;
        } else {
            ad0 = ald[node];
        }
    }

    int jj = beg + lane;
    bool have = active && (jj < end);
    int sreg = 0;
    float s0 = 0.f, s1 = 0.f, s2 = 0.f, s3 = 0.f;
    if (have) {
        sreg = csrc[jj];
        float4 e;
        if (H == 4) {
            float4 a = *(const float4*)&als[sreg * 4];
            e.x = __expf(lrelu(a.x + ad0));
            e.y = __expf(lrelu(a.y + ad1));
            e.z = __expf(lrelu(a.z + ad2));
            e.w = __expf(lrelu(a.w + ad3));
            s0 += e.x; s1 += e.y; s2 += e.z; s3 += e.w;
        } else {
            e.x = __expf(lrelu(als[sreg] + ad0));
            e.y = e.z = e.w = 0.f;
            s0 += e.x;
        }
        sE[w * 32 + lane] = e;
        sS[w * 32 + lane] = sreg;
    }
    for (int j = jj + 32; j < end; j += 32) {
        int s = csrc[j];
        if (H == 4) {
            float4 a = *(const float4*)&als[s * 4];
            s0 += __expf(lrelu(a.x + ad0));
            s1 += __expf(lrelu(a.y + ad1));
            s2 += __expf(lrelu(a.z + ad2));
            s3 += __expf(lrelu(a.w + ad3));
        } else {
            s0 += __expf(lrelu(als[s] + ad0));
        }
    }
#pragma unroll
    for (int o = 16; o; o >>= 1) {
        s0 += __shfl_xor_sync(0xffffffffu, s0, o);
        if (H == 4) {
            s1 += __shfl_xor_sync(0xffffffffu, s1, o);
            s2 += __shfl_xor_sync(0xffffffffu, s2, o);
            s3 += __shfl_xor_sync(0xffffffffu, s3, o);
        }
    }
    __syncwarp();

    int cnt_e = end - beg;
    int cached = cnt_e < 32 ? cnt_e : 32;

    if (H == 4) {
        float r0 = 1.f / (s0 + 1e-16f), r1 = 1.f / (s1 + 1e-16f);
        float r2 = 1.f / (s2 + 1e-16f), r3 = 1.f / (s3 + 1e-16f);
        int head = lane >> 3;
        float rv  = lane < 16 ? (lane < 8 ? r0 : r1) : (lane < 24 ? r2 : r3);
        float adh = lane < 16 ? (lane < 8 ? ad0 : ad1) : (lane < 24 ? ad2 : ad3);

        float4 acc = make_float4(0.f, 0.f, 0.f, 0.f);
        const float* eb = (const float*)&sE[w * 32];
        const int*   sb = &sS[w * 32];
        int j2 = 0;
        for (; j2 + 4 <= cached; j2 += 4) {
            int sA = sb[j2], sB = sb[j2 + 1], sC = sb[j2 + 2], sD = sb[j2 + 3];
            float evA = eb[(j2 + 0) * 4 + head];
            float evB = eb[(j2 + 1) * 4 + head];
            float evC = eb[(j2 + 2) * 4 + head];
            float evD = eb[(j2 + 3) * 4 + head];
            float4 hA = *(const float4*)&h[(size_t)sA * 128 + lane * 4];
            float4 hB = *(const float4*)&h[(size_t)sB * 128 + lane * 4];
            float4 hC = *(const float4*)&h[(size_t)sC * 128 + lane * 4];
            float4 hD = *(const float4*)&h[(size_t)sD * 128 + lane * 4];
            acc.x += hA.x * evA + hB.x * evB + hC.x * evC + hD.x * evD;
            acc.y += hA.y * evA + hB.y * evB + hC.y * evC + hD.y * evD;
            acc.z += hA.z * evA + hB.z * evB + hC.z * evC + hD.z * evD;
            acc.w += hA.w * evA + hB.w * evB + hC.w * evC + hD.w * evD;
        }
        for (; j2 < cached; j2++) {
            int sA = sb[j2];
            float evA = eb[j2 * 4 + head];
            float4 hA = *(const float4*)&h[(size_t)sA * 128 + lane * 4];
            acc.x += hA.x * evA; acc.y += hA.y * evA;
            acc.z += hA.z * evA; acc.w += hA.w * evA;
        }
        for (int j = beg + 32; j < end; j++) {
            int s = csrc[j];
            float4 a = *(const float4*)&als[s * 4];
            float ah = lane < 16 ? (lane < 8 ? a.x : a.y) : (lane < 24 ? a.z : a.w);
            float ev = __expf(lrelu(ah + adh));
            float4 hv = *(const float4*)&h[(size_t)s * 128 + lane * 4];
            acc.x += hv.x * ev; acc.y += hv.y * ev;
            acc.z += hv.z * ev; acc.w += hv.w * ev;
        }
        float4 bi = active ? *(const float4*)&bias[lane * 4]
                           : make_float4(0.f, 0.f, 0.f, 0.f);
        float4 ov;
        ov.x = acc.x * rv + bi.x;
        ov.y = acc.y * rv + bi.y;
        ov.z = acc.z * rv + bi.z;
        ov.w = acc.w * rv + bi.w;
        if (active) *(float4*)&out[(size_t)node * 128 + lane * 4] = ov;

        if (STATS) {
            if (active) {
                int ch = lane * 4;
                atomicAdd(&sred[ch + 0], ov.x);
                atomicAdd(&sred[ch + 1], ov.y);
                atomicAdd(&sred[ch + 2], ov.z);
                atomicAdd(&sred[ch + 3], ov.w);
                atomicAdd(&sred[HD_ + ch + 0], ov.x * ov.x);
                atomicAdd(&sred[HD_ + ch + 1], ov.y * ov.y);
                atomicAdd(&sred[HD_ + ch + 2], ov.z * ov.z);
                atomicAdd(&sred[HD_ + ch + 3], ov.w * ov.w);
            }
            __syncthreads();
            if (t < 2 * HD_) atomicAdd(&bn[t], sred[t]);
        }
    } else {
        float r0 = 1.f / (s0 + 1e-16f);
        float2 acc = make_float2(0.f, 0.f);
        const float* eb = (const float*)&sE[w * 32];
        const int*   sb = &sS[w * 32];
        int j2 = 0;
        for (; j2 + 4 <= cached; j2 += 4) {
            int sA = sb[j2], sB = sb[j2 + 1], sC = sb[j2 + 2], sD = sb[j2 + 3];
            float eA = eb[(j2 + 0) * 4];
            float eB = eb[(j2 + 1) * 4];
            float eC = eb[(j2 + 2) * 4];
            float eD = eb[(j2 + 3) * 4];
            float2 hA = *(const float2*)&h[(size_t)sA * 64 + lane * 2];
            float2 hB = *(const float2*)&h[(size_t)sB * 64 + lane * 2];
            float2 hC = *(const float2*)&h[(size_t)sC * 64 + lane * 2];
            float2 hD = *(const float2*)&h[(size_t)sD * 64 + lane * 2];
            acc.x += hA.x * eA + hB.x * eB + hC.x * eC + hD.x * eD;
            acc.y += hA.y * eA + hB.y * eB + hC.y * eC + hD.y * eD;
        }
        for (; j2 < cached; j2++) {
            int sA = sb[j2];
            float eA = eb[j2 * 4];
            float2 hA = *(const float2*)&h[(size_t)sA * 64 + lane * 2];
            acc.x += hA.x * eA;
            acc.y += hA.y * eA;
        }
        for (int j = beg + 32; j < end; j++) {
            int s = csrc[j];
            float ev = __expf(lrelu(als[s] + ad0));
            float2 hv = *(const float2*)&h[(size_t)s * 64 + lane * 2];
            acc.x += hv.x * ev;
            acc.y += hv.y * ev;
        }
        if (active) {
            float2 bi = *(const float2*)&bias[lane * 2];
            float2 ov;
            ov.x = acc.x * r0 + bi.x;
            ov.y = acc.y * r0 + bi.y;
            *(float2*)&out[(size_t)node * 64 + lane * 2] = ov;
            if (POOL) {
                int g = __ldg(&bid[node]);          // warp-uniform
                atomicAdd(&pool[g * OUTC + lane * 2],     ov.x);
                atomicAdd(&pool[g * OUTC + lane * 2 + 1], ov.y);
                if (lane == 0) atomicAdd(&cnt[g], 1.f);
            }
        }
    }
}

// ---------------- BN finalize (self-clearing; optionally clears pool) -------
__global__ void bn_finalize(float* __restrict__ bn, const float* __restrict__ g,
                            const float* __restrict__ be, float* __restrict__ pool,
                            float* __restrict__ cnt, int clearPool) {
    int j = threadIdx.x;
    float mu = bn[j] / (float)NN;
    float var = bn[HD_ + j] / (float)NN - mu * mu;
    float sc = __ldg(&g[j]) * rsqrtf(var + 1e-5f);
    bn[2 * HD_ + j] = sc;
    bn[3 * HD_ + j] = __ldg(&be[j]) - mu * sc;
    bn[j] = 0.f;
    bn[HD_ + j] = 0.f;
    if (clearPool) {
        for (int i = j; i < NGRP * OUTC; i += HD_) pool[i] = 0.f;
        if (j < NGRP) cnt[j] = 0.f;
    }
}

__global__ void pool_fin(const float* __restrict__ pool, const float* __restrict__ cnt,
                         float* __restrict__ out) {
    int i = blockIdx.x * blockDim.x + threadIdx.x;
    if (i >= NGRP * OUTC) return;
    float c = cnt[i >> 6];
    out[i] = pool[i] / fmaxf(c, 1.f);
}

// ---------------- host ----------------
extern "C" void kernel_launch(void* const* d_in, const int* in_sizes, int n_in,
                              void* d_out, int out_size) {
    const float* x   = (const float*)d_in[0];
    const int*   ei  = (const int*)d_in[1];
    const int*   bid = (const int*)d_in[2];
    const float *W[4], *As[4], *Ad[4], *B[4];
    for (int i = 0; i < 4; i++) {
        W[i]  = (const float*)d_in[3 + 4 * i];
        As[i] = (const float*)d_in[4 + 4 * i];
        Ad[i] = (const float*)d_in[5 + 4 * i];
        B[i]  = (const float*)d_in[6 + 4 * i];
    }
    const float *G[3], *Be[3];
    for (int i = 0; i < 3; i++) {
        G[i]  = (const float*)d_in[19 + 2 * i];
        Be[i] = (const float*)d_in[20 + 2 * i];
    }
    int E  = in_sizes[1] / 2;
    int ET = E + NN;

    float *h_, *agg_, *als_, *ald_, *bn_, *pool_, *cnt_;
    int *deg_, *roff_, *cur_, *csrc_;
    cudaGetSymbolAddress((void**)&h_,    g_h);
    cudaGetSymbolAddress((void**)&agg_,  g_agg);
    cudaGetSymbolAddress((void**)&als_,  g_als);
    cudaGetSymbolAddress((void**)&ald_,  g_ald);
    cudaGetSymbolAddress((void**)&deg_,  g_deg);
    cudaGetSymbolAddress((void**)&roff_, g_roff);
    cudaGetSymbolAddress((void**)&cur_,  g_cur);
    cudaGetSymbolAddress((void**)&csrc_, g_csrc);
    cudaGetSymbolAddress((void**)&bn_,   g_bn);
    cudaGetSymbolAddress((void**)&pool_, g_pool);
    cudaGetSymbolAddress((void**)&cnt_,  g_cnt);

    const int TB = 256;
    const int AGG_BLOCKS = ceil_div(NN * 32, TB);
    const int GB = ceil_div(NN, 32);

    // ---- CSR build; layer-0 GEMM hoisted before scatter (profile slot) ----
    clear_i<<<128, TB>>>(deg_, NN);
    hist_k<<<1024, TB>>>(ei, deg_, E, ET);
    scan_k<<<1, 1024>>>(deg_, roff_, cur_);
    gemm_attn_k<128, false, 4, 32><<<GB, 128>>>(x, W[0], bn_, As[0], Ad[0],
                                                h_, als_, ald_, NN);
    scatter_k<<<1024, TB>>>(ei, cur_, csrc_, E, ET);

    // ---- layer 0 aggregation ----
    aggregate_k<4, 128, true, false><<<AGG_BLOCKS, TB>>>(roff_, csrc_, h_, als_, ald_,
                                                         B[0], agg_, bn_, bid, pool_, cnt_);
    bn_finalize<<<1, HD_>>>(bn_, G[0], Be[0], pool_, cnt_, 0);

    // ---- layers 1,2 ----
    for (int l = 1; l < 3; l++) {
        gemm_attn_k<128, true, 4, 32><<<GB, 128>>>(agg_, W[l], bn_, As[l], Ad[l],
                                                   h_, als_, ald_, NN);
        aggregate_k<4, 128, true, false><<<AGG_BLOCKS, TB>>>(roff_, csrc_, h_, als_, ald_,
                                                             B[l], agg_, bn_, bid, pool_, cnt_);
        bn_finalize<<<1, HD_>>>(bn_, G[l], Be[l], pool_, cnt_, l == 2);
    }

    // ---- layer 3 (H=1, OUT=64) with fused pool accumulation ----
    gemm_attn_k<64, true, 1, 64><<<GB, 64>>>(agg_, W[3], bn_, As[3], Ad[3],
                                             h_, als_, ald_, NN);
    aggregate_k<1, 64, false, true><<<AGG_BLOCKS, TB>>>(roff_, csrc_, h_, als_, ald_,
                                                        B[3], agg_, bn_, bid, pool_, cnt_);

    pool_fin<<<ceil_div(NGRP * OUTC, TB), TB>>>(pool_, cnt_, (float*)d_out);
}

// round 12
// speedup vs baseline: 1.1911x; 1.0716x over previous
#include <cuda_runtime.h>
#include <cuda_bf16.h>

#define NN     50000
#define HD_    128
#define EMAX   800000
#define ETMAX  (EMAX + NN)
#define NGRP   64
#define OUTC   64

// ---------------- scratch ----------------
__device__ __nv_bfloat16 g_h[NN * HD_];   // bf16 message payload
__device__ float  g_agg[NN * HD_];
__device__ float  g_als[NN * 4];
__device__ float  g_ald[NN * 4];
__device__ int    g_deg[NN];
__device__ int    g_roff[NN + 1];
__device__ int    g_cur[NN];
__device__ int    g_csrc[ETMAX];
__device__ float  g_bn[4 * HD_];   // sum | sumsq | scale | shift
__device__ float  g_pool[NGRP * OUTC];
__device__ float  g_cnt[NGRP];

static inline int ceil_div(int a, int b) { return (a + b - 1) / b; }

__device__ __forceinline__ float lrelu(float v) { return v > 0.f ? v : 0.2f * v; }
__device__ __forceinline__ float elu_f(float y) { return y > 0.f ? y : __expf(y) - 1.f; }

// ---------------- misc ----------------
__global__ void clear_i(int* p, int n) {
    for (int i = blockIdx.x * blockDim.x + threadIdx.x; i < n; i += gridDim.x * blockDim.x)
        p[i] = 0;
}

// ---------------- CSR build ----------------
__global__ void hist_k(const int* __restrict__ ei, int* __restrict__ deg, int E, int ET) {
    for (int e = blockIdx.x * blockDim.x + threadIdx.x; e < ET; e += gridDim.x * blockDim.x) {
        int d = (e < E) ? __ldg(&ei[E + e]) : (e - E);
        atomicAdd(&deg[d], 1);
    }
}

__global__ void scan_k(const int* __restrict__ deg, int* __restrict__ roff,
                       int* __restrict__ cur) {
    __shared__ int ssum[1024];
    int tid = threadIdx.x;
    const int CH = (NN + 1023) / 1024;
    int base = tid * CH;
    int s = 0;
    for (int i = 0; i < CH; i++) {
        int n = base + i;
        if (n < NN) s += deg[n];
    }
    ssum[tid] = s;
    __syncthreads();
    for (int off = 1; off < 1024; off <<= 1) {
        int v = 0;
        if (tid >= off) v = ssum[tid - off];
        __syncthreads();
        if (tid >= off) ssum[tid] += v;
        __syncthreads();
    }
    int run = (tid == 0) ? 0 : ssum[tid - 1];
    for (int i = 0; i < CH; i++) {
        int n = base + i;
        if (n < NN) {
            roff[n] = run;
            cur[n]  = run;
            run += deg[n];
        }
    }
    if (tid == 1023) roff[NN] = ssum[1023];
}

__global__ void scatter_k(const int* __restrict__ ei, int* __restrict__ cur,
                          int* __restrict__ csrc, int E, int ET) {
    for (int e = blockIdx.x * blockDim.x + threadIdx.x; e < ET; e += gridDim.x * blockDim.x) {
        int s, d;
        if (e < E) { s = __ldg(&ei[e]); d = __ldg(&ei[E + e]); }
        else       { s = d = e - E; }
        int pos = atomicAdd(&cur[d], 1);
        csrc[pos] = s;
    }
}

// ---------------- GEMM + fused attention logits; h stored bf16 --------------
// Logits computed fp32 from the smem tile (full precision); only the gathered
// message payload is rounded to bf16.
template <int M, bool BNIN, int H, int C>
__global__ __launch_bounds__(128, 7)
void gemm_attn_k(const float* __restrict__ A, const float* __restrict__ W,
                 const float* __restrict__ bn,
                 const float* __restrict__ a_s, const float* __restrict__ a_d,
                 __nv_bfloat16* __restrict__ Cout, float* __restrict__ als,
                 float* __restrict__ ald, int rows) {
    __shared__ float sm[4224];   // phase A: xs[32][128]; phase B: hs[32][M+4]
    int row0 = blockIdx.x * 32;
    int t = threadIdx.x;
    const int CG = M / 4;
    int cg = t % CG;
    int rg = t / CG;   // 0..3

    for (int i = t; i < 32 * 32; i += M) {
        int r = i >> 5, c4 = i & 31;
        float4 v = make_float4(0.f, 0.f, 0.f, 0.f);
        if (row0 + r < rows) {
            v = *(const float4*)&A[(size_t)(row0 + r) * 128 + c4 * 4];
            if (BNIN) {
                float4 sc = *(const float4*)&bn[2 * HD_ + c4 * 4];
                float4 sh = *(const float4*)&bn[3 * HD_ + c4 * 4];
                v.x = elu_f(v.x * sc.x + sh.x);
                v.y = elu_f(v.y * sc.y + sh.y);
                v.z = elu_f(v.z * sc.z + sh.z);
                v.w = elu_f(v.w * sc.w + sh.w);
            }
        }
        *(float4*)&sm[r * 128 + c4 * 4] = v;
    }
    __syncthreads();

    float acc[8][4];
#pragma unroll
    for (int r = 0; r < 8; r++)
#pragma unroll
        for (int j = 0; j < 4; j++) acc[r][j] = 0.f;

    const float4* xs4 = (const float4*)sm;
#pragma unroll 4
    for (int k4 = 0; k4 < 32; k4++) {
        float4 w0 = __ldg((const float4*)&W[(size_t)(k4 * 4 + 0) * M + cg * 4]);
        float4 w1 = __ldg((const float4*)&W[(size_t)(k4 * 4 + 1) * M + cg * 4]);
        float4 w2 = __ldg((const float4*)&W[(size_t)(k4 * 4 + 2) * M + cg * 4]);
        float4 w3 = __ldg((const float4*)&W[(size_t)(k4 * 4 + 3) * M + cg * 4]);
#pragma unroll
        for (int r = 0; r < 8; r++) {
            float4 xv = xs4[(rg * 8 + r) * 32 + k4];
            acc[r][0] += xv.x * w0.x + xv.y * w1.x + xv.z * w2.x + xv.w * w3.x;
            acc[r][1] += xv.x * w0.y + xv.y * w1.y + xv.z * w2.y + xv.w * w3.y;
            acc[r][2] += xv.x * w0.z + xv.y * w1.z + xv.z * w2.z + xv.w * w3.z;
            acc[r][3] += xv.x * w0.w + xv.y * w1.w + xv.z * w2.w + xv.w * w3.w;
        }
    }
    __syncthreads();   // xs no longer needed; reuse sm as hs[32][M+4]

    const int LD = M + 4;
#pragma unroll
    for (int r = 0; r < 8; r++) {
        int row = rg * 8 + r;
        float4 o = make_float4(acc[r][0], acc[r][1], acc[r][2], acc[r][3]);
        *(float4*)&sm[row * LD + cg * 4] = o;
        if (row0 + row < rows) {
            __nv_bfloat162 b0 = __float22bfloat162_rn(make_float2(o.x, o.y));
            __nv_bfloat162 b1 = __float22bfloat162_rn(make_float2(o.z, o.w));
            uint2 pk;
            pk.x = *(unsigned*)&b0;
            pk.y = *(unsigned*)&b1;
            *(uint2*)&Cout[(size_t)(row0 + row) * M + cg * 4] = pk;
        }
    }
    __syncthreads();

    if (H == 4) {
        int row = t & 31, head = t >> 5;   // warp-uniform head
        const float4* hrow = (const float4*)&sm[row * LD + head * C];
        const float4* ap = (const float4*)(a_s + head * C);
        const float4* dp = (const float4*)(a_d + head * C);
        float s1 = 0.f, s2 = 0.f;
#pragma unroll
        for (int c4 = 0; c4 < C / 4; c4++) {
            float4 v = hrow[c4];
            float4 a = __ldg(&ap[c4]);
            float4 d = __ldg(&dp[c4]);
            s1 += v.x * a.x + v.y * a.y + v.z * a.z + v.w * a.w;
            s2 += v.x * d.x + v.y * d.y + v.z * d.z + v.w * d.w;
        }
        int gr = row0 + row;
        if (gr < rows) {
            als[gr * 4 + head] = s1;
            ald[gr * 4 + head] = s2;
        }
    } else {
        int row = t & 31, sel = t >> 5;
        const float4* av = (const float4*)(sel ? a_d : a_s);
        const float4* hrow = (const float4*)&sm[row * LD];
        float acc1 = 0.f;
#pragma unroll
        for (int c4 = 0; c4 < C / 4; c4++) {
            float4 v = hrow[c4];
            float4 a = __ldg(&av[c4]);
            acc1 += v.x * a.x + v.y * a.y + v.z * a.z + v.w * a.w;
        }
        int gr = row0 + row;
        if (gr < rows) {
            if (sel) ald[gr] = acc1; else als[gr] = acc1;
        }
    }
}

__device__ __forceinline__ float4 bf4_to_f4(uint2 pk) {
    __nv_bfloat162 b0 = *(__nv_bfloat162*)&pk.x;
    __nv_bfloat162 b1 = *(__nv_bfloat162*)&pk.y;
    float2 f0 = __bfloat1622float2(b0);
    float2 f1 = __bfloat1622float2(b1);
    return make_float4(f0.x, f0.y, f1.x, f1.y);
}
__device__ __forceinline__ float2 bf2_to_f2(unsigned pk) {
    __nv_bfloat162 b = *(__nv_bfloat162*)&pk;
    return __bfloat1622float2(b);
}

// ---------------- fused per-node GAT aggregation (warp per node) ------------
template <int H, int M, bool STATS, bool POOL>
__global__ void aggregate_k(const int* __restrict__ roff, const int* __restrict__ csrc,
                            const __nv_bfloat16* __restrict__ h,
                            const float* __restrict__ als,
                            const float* __restrict__ ald, const float* __restrict__ bias,
                            float* __restrict__ out, float* __restrict__ bn,
                            const int* __restrict__ bid, float* __restrict__ pool,
                            float* __restrict__ cnt) {
    __shared__ float sred[2 * HD_];
    __shared__ float4 sE[8 * 32];
    __shared__ int    sS[8 * 32];
    int t = threadIdx.x;
    if (STATS) {
        if (t < 2 * HD_) sred[t] = 0.f;
        __syncthreads();
    }
    int node = (blockIdx.x * blockDim.x + t) >> 5;
    int lane = t & 31;
    int w = t >> 5;
    bool active = (node < NN);
    int beg = 0, end = 0;
    if (active) { beg = roff[node]; end = roff[node + 1]; }

    float ad0 = 0.f, ad1 = 0.f, ad2 = 0.f, ad3 = 0.f;
    if (active) {
        if (H == 4) {
            float4 tt = *(const float4*)&ald[node * 4];
            ad0 = tt.x; ad1 = tt.y; ad2 = tt.z; ad3 = tt.w;
        } else {
            ad0 = ald[node];
        }
    }

    int jj = beg + lane;
    bool have = active && (jj < end);
    int sreg = 0;
    float s0 = 0.f, s1 = 0.f, s2 = 0.f, s3 = 0.f;
    if (have) {
        sreg = csrc[jj];
        float4 e;
        if (H == 4) {
            float4 a = *(const float4*)&als[sreg * 4];
            e.x = __expf(lrelu(a.x + ad0));
            e.y = __expf(lrelu(a.y + ad1));
            e.z = __expf(lrelu(a.z + ad2));
            e.w = __expf(lrelu(a.w + ad3));
            s0 += e.x; s1 += e.y; s2 += e.z; s3 += e.w;
        } else {
            e.x = __expf(lrelu(als[sreg] + ad0));
            e.y = e.z = e.w = 0.f;
            s0 += e.x;
        }
        sE[w * 32 + lane] = e;
        sS[w * 32 + lane] = sreg;
    }
    for (int j = jj + 32; j < end; j += 32) {
        int s = csrc[j];
        if (H == 4) {
            float4 a = *(const float4*)&als[s * 4];
            s0 += __expf(lrelu(a.x + ad0));
            s1 += __expf(lrelu(a.y + ad1));
            s2 += __expf(lrelu(a.z + ad2));
            s3 += __expf(lrelu(a.w + ad3));
        } else {
            s0 += __expf(lrelu(als[s] + ad0));
        }
    }
#pragma unroll
    for (int o = 16; o; o >>= 1) {
        s0 += __shfl_xor_sync(0xffffffffu, s0, o);
        if (H == 4) {
            s1 += __shfl_xor_sync(0xffffffffu, s1, o);
            s2 += __shfl_xor_sync(0xffffffffu, s2, o);
            s3 += __shfl_xor_sync(0xffffffffu, s3, o);
        }
    }
    __syncwarp();

    int cnt_e = end - beg;
    int cached = cnt_e < 32 ? cnt_e : 32;

    if (H == 4) {
        float r0 = 1.f / (s0 + 1e-16f), r1 = 1.f / (s1 + 1e-16f);
        float r2 = 1.f / (s2 + 1e-16f), r3 = 1.f / (s3 + 1e-16f);
        int head = lane >> 3;
        float rv  = lane < 16 ? (lane < 8 ? r0 : r1) : (lane < 24 ? r2 : r3);
        float adh = lane < 16 ? (lane < 8 ? ad0 : ad1) : (lane < 24 ? ad2 : ad3);

        float4 acc = make_float4(0.f, 0.f, 0.f, 0.f);
        const float* eb = (const float*)&sE[w * 32];
        const int*   sb = &sS[w * 32];
        int j2 = 0;
        for (; j2 + 4 <= cached; j2 += 4) {
            int sA = sb[j2], sB = sb[j2 + 1], sC = sb[j2 + 2], sD = sb[j2 + 3];
            float evA = eb[(j2 + 0) * 4 + head];
            float evB = eb[(j2 + 1) * 4 + head];
            float evC = eb[(j2 + 2) * 4 + head];
            float evD = eb[(j2 + 3) * 4 + head];
            uint2 pA = *(const uint2*)&h[(size_t)sA * 128 + lane * 4];
            uint2 pB = *(const uint2*)&h[(size_t)sB * 128 + lane * 4];
            uint2 pC = *(const uint2*)&h[(size_t)sC * 128 + lane * 4];
            uint2 pD = *(const uint2*)&h[(size_t)sD * 128 + lane * 4];
            float4 hA = bf4_to_f4(pA), hB = bf4_to_f4(pB);
            float4 hC = bf4_to_f4(pC), hD = bf4_to_f4(pD);
            acc.x += hA.x * evA + hB.x * evB + hC.x * evC + hD.x * evD;
            acc.y += hA.y * evA + hB.y * evB + hC.y * evC + hD.y * evD;
            acc.z += hA.z * evA + hB.z * evB + hC.z * evC + hD.z * evD;
            acc.w += hA.w * evA + hB.w * evB + hC.w * evC + hD.w * evD;
        }
        for (; j2 < cached; j2++) {
            int sA = sb[j2];
            float evA = eb[j2 * 4 + head];
            float4 hA = bf4_to_f4(*(const uint2*)&h[(size_t)sA * 128 + lane * 4]);
            acc.x += hA.x * evA; acc.y += hA.y * evA;
            acc.z += hA.z * evA; acc.w += hA.w * evA;
        }
        for (int j = beg + 32; j < end; j++) {
            int s = csrc[j];
            float4 a = *(const float4*)&als[s * 4];
            float ah = lane < 16 ? (lane < 8 ? a.x : a.y) : (lane < 24 ? a.z : a.w);
            float ev = __expf(lrelu(ah + adh));
            float4 hv = bf4_to_f4(*(const uint2*)&h[(size_t)s * 128 + lane * 4]);
            acc.x += hv.x * ev; acc.y += hv.y * ev;
            acc.z += hv.z * ev; acc.w += hv.w * ev;
        }
        float4 bi = active ? *(const float4*)&bias[lane * 4]
                           : make_float4(0.f, 0.f, 0.f, 0.f);
        float4 ov;
        ov.x = acc.x * rv + bi.x;
        ov.y = acc.y * rv + bi.y;
        ov.z = acc.z * rv + bi.z;
        ov.w = acc.w * rv + bi.w;
        if (active) *(float4*)&out[(size_t)node * 128 + lane * 4] = ov;

        if (STATS) {
            if (active) {
                int ch = lane * 4;
                atomicAdd(&sred[ch + 0], ov.x);
                atomicAdd(&sred[ch + 1], ov.y);
                atomicAdd(&sred[ch + 2], ov.z);
                atomicAdd(&sred[ch + 3], ov.w);
                atomicAdd(&sred[HD_ + ch + 0], ov.x * ov.x);
                atomicAdd(&sred[HD_ + ch + 1], ov.y * ov.y);
                atomicAdd(&sred[HD_ + ch + 2], ov.z * ov.z);
                atomicAdd(&sred[HD_ + ch + 3], ov.w * ov.w);
            }
            __syncthreads();
            if (t < 2 * HD_) atomicAdd(&bn[t], sred[t]);
        }
    } else {
        float r0 = 1.f / (s0 + 1e-16f);
        float2 acc = make_float2(0.f, 0.f);
        const float* eb = (const float*)&sE[w * 32];
        const int*   sb = &sS[w * 32];
        int j2 = 0;
        for (; j2 + 4 <= cached; j2 += 4) {
            int sA = sb[j2], sB = sb[j2 + 1], sC = sb[j2 + 2], sD = sb[j2 + 3];
            float eA = eb[(j2 + 0) * 4];
            float eB = eb[(j2 + 1) * 4];
            float eC = eb[(j2 + 2) * 4];
            float eD = eb[(j2 + 3) * 4];
            float2 hA = bf2_to_f2(*(const unsigned*)&h[(size_t)sA * 64 + lane * 2]);
            float2 hB = bf2_to_f2(*(const unsigned*)&h[(size_t)sB * 64 + lane * 2]);
            float2 hC = bf2_to_f2(*(const unsigned*)&h[(size_t)sC * 64 + lane * 2]);
            float2 hD = bf2_to_f2(*(const unsigned*)&h[(size_t)sD * 64 + lane * 2]);
            acc.x += hA.x * eA + hB.x * eB + hC.x * eC + hD.x * eD;
            acc.y += hA.y * eA + hB.y * eB + hC.y * eC + hD.y * eD;
        }
        for (; j2 < cached; j2++) {
            int sA = sb[j2];
            float eA = eb[j2 * 4];
            float2 hA = bf2_to_f2(*(const unsigned*)&h[(size_t)sA * 64 + lane * 2]);
            acc.x += hA.x * eA;
            acc.y += hA.y * eA;
        }
        for (int j = beg + 32; j < end; j++) {
            int s = csrc[j];
            float ev = __expf(lrelu(als[s] + ad0));
            float2 hv = bf2_to_f2(*(const unsigned*)&h[(size_t)s * 64 + lane * 2]);
            acc.x += hv.x * ev;
            acc.y += hv.y * ev;
        }
        if (active) {
            float2 bi = *(const float2*)&bias[lane * 2];
            float2 ov;
            ov.x = acc.x * r0 + bi.x;
            ov.y = acc.y * r0 + bi.y;
            *(float2*)&out[(size_t)node * 64 + lane * 2] = ov;
            if (POOL) {
                int g = __ldg(&bid[node]);          // warp-uniform
                atomicAdd(&pool[g * OUTC + lane * 2],     ov.x);
                atomicAdd(&pool[g * OUTC + lane * 2 + 1], ov.y);
                if (lane == 0) atomicAdd(&cnt[g], 1.f);
            }
        }
    }
}

// ---------------- BN finalize (self-clearing; optionally clears pool) -------
__global__ void bn_finalize(float* __restrict__ bn, const float* __restrict__ g,
                            const float* __restrict__ be, float* __restrict__ pool,
                            float* __restrict__ cnt, int clearPool) {
    int j = threadIdx.x;
    float mu = bn[j] / (float)NN;
    float var = bn[HD_ + j] / (float)NN - mu * mu;
    float sc = __ldg(&g[j]) * rsqrtf(var + 1e-5f);
    bn[2 * HD_ + j] = sc;
    bn[3 * HD_ + j] = __ldg(&be[j]) - mu * sc;
    bn[j] = 0.f;
    bn[HD_ + j] = 0.f;
    if (clearPool) {
        for (int i = j; i < NGRP * OUTC; i += HD_) pool[i] = 0.f;
        if (j < NGRP) cnt[j] = 0.f;
    }
}

__global__ void pool_fin(const float* __restrict__ pool, const float* __restrict__ cnt,
                         float* __restrict__ out) {
    int i = blockIdx.x * blockDim.x + threadIdx.x;
    if (i >= NGRP * OUTC) return;
    float c = cnt[i >> 6];
    out[i] = pool[i] / fmaxf(c, 1.f);
}

// ---------------- host ----------------
extern "C" void kernel_launch(void* const* d_in, const int* in_sizes, int n_in,
                              void* d_out, int out_size) {
    const float* x   = (const float*)d_in[0];
    const int*   ei  = (const int*)d_in[1];
    const int*   bid = (const int*)d_in[2];
    const float *W[4], *As[4], *Ad[4], *B[4];
    for (int i = 0; i < 4; i++) {
        W[i]  = (const float*)d_in[3 + 4 * i];
        As[i] = (const float*)d_in[4 + 4 * i];
        Ad[i] = (const float*)d_in[5 + 4 * i];
        B[i]  = (const float*)d_in[6 + 4 * i];
    }
    const float *G[3], *Be[3];
    for (int i = 0; i < 3; i++) {
        G[i]  = (const float*)d_in[19 + 2 * i];
        Be[i] = (const float*)d_in[20 + 2 * i];
    }
    int E  = in_sizes[1] / 2;
    int ET = E + NN;

    __nv_bfloat16* h_;
    float *agg_, *als_, *ald_, *bn_, *pool_, *cnt_;
    int *deg_, *roff_, *cur_, *csrc_;
    cudaGetSymbolAddress((void**)&h_,    g_h);
    cudaGetSymbolAddress((void**)&agg_,  g_agg);
    cudaGetSymbolAddress((void**)&als_,  g_als);
    cudaGetSymbolAddress((void**)&ald_,  g_ald);
    cudaGetSymbolAddress((void**)&deg_,  g_deg);
    cudaGetSymbolAddress((void**)&roff_, g_roff);
    cudaGetSymbolAddress((void**)&cur_,  g_cur);
    cudaGetSymbolAddress((void**)&csrc_, g_csrc);
    cudaGetSymbolAddress((void**)&bn_,   g_bn);
    cudaGetSymbolAddress((void**)&pool_, g_pool);
    cudaGetSymbolAddress((void**)&cnt_,  g_cnt);

    const int TB = 256;
    const int AGG_BLOCKS = ceil_div(NN * 32, TB);
    const int GB = ceil_div(NN, 32);

    // ---- CSR build; layer-0 GEMM hoisted before scatter (profile slot) ----
    clear_i<<<128, TB>>>(deg_, NN);
    hist_k<<<1024, TB>>>(ei, deg_, E, ET);
    scan_k<<<1, 1024>>>(deg_, roff_, cur_);
    gemm_attn_k<128, false, 4, 32><<<GB, 128>>>(x, W[0], bn_, As[0], Ad[0],
                                                h_, als_, ald_, NN);
    scatter_k<<<1024, TB>>>(ei, cur_, csrc_, E, ET);

    // ---- layer 0 aggregation ----
    aggregate_k<4, 128, true, false><<<AGG_BLOCKS, TB>>>(roff_, csrc_, h_, als_, ald_,
                                                         B[0], agg_, bn_, bid, pool_, cnt_);
    bn_finalize<<<1, HD_>>>(bn_, G[0], Be[0], pool_, cnt_, 0);

    // ---- layers 1,2 ----
    for (int l = 1; l < 3; l++) {
        gemm_attn_k<128, true, 4, 32><<<GB, 128>>>(agg_, W[l], bn_, As[l], Ad[l],
                                                   h_, als_, ald_, NN);
        aggregate_k<4, 128, true, false><<<AGG_BLOCKS, TB>>>(roff_, csrc_, h_, als_, ald_,
                                                             B[l], agg_, bn_, bid, pool_, cnt_);
        bn_finalize<<<1, HD_>>>(bn_, G[l], Be[l], pool_, cnt_, l == 2);
    }

    // ---- layer 3 (H=1, OUT=64) with fused pool accumulation ----
    gemm_attn_k<64, true, 1, 64><<<GB, 64>>>(agg_, W[3], bn_, As[3], Ad[3],
                                             h_, als_, ald_, NN);
    aggregate_k<1, 64, false, true><<<AGG_BLOCKS, TB>>>(roff_, csrc_, h_, als_, ald_,
                                                        B[3], agg_, bn_, bid, pool_, cnt_);

    pool_fin<<<ceil_div(NGRP * OUTC, TB), TB>>>(pool_, cnt_, (float*)d_out);
}

// round 13
// speedup vs baseline: 1.4374x; 1.2068x over previous
#include <cuda_runtime.h>
#include <cuda_bf16.h>
#include <cstdint>

#define NN     50000
#define HD_    128
#define EMAX   800000
#define ETMAX  (EMAX + NN)
#define NGRP   64
#define OUTC   64

// ---------------- scratch ----------------
__device__ __nv_bfloat16 g_h[NN * HD_];   // bf16 message payload
__device__ float  g_agg[NN * HD_];
__device__ float  g_als[NN * 4];
__device__ float  g_ald[NN * 4];
__device__ int    g_deg[NN];
__device__ int    g_roff[NN + 1];
__device__ int    g_cur[NN];
__device__ int    g_csrc[ETMAX];
__device__ float  g_bn[4 * HD_];   // sum | sumsq | scale | shift
__device__ float  g_pool[NGRP * OUTC];
__device__ float  g_cnt[NGRP];
__device__ float  g_wpack[4 * 16384];   // per-layer fragment-packed W (bf16 hi/lo)

static inline int ceil_div(int a, int b) { return (a + b - 1) / b; }

__device__ __forceinline__ float lrelu(float v) { return v > 0.f ? v : 0.2f * v; }
__device__ __forceinline__ float elu_f(float y) { return y > 0.f ? y : __expf(y) - 1.f; }

__device__ __forceinline__ unsigned smaddr(const void* p) {
    return (unsigned)__cvta_generic_to_shared(p);
}

#define LDMATRIX_X4(r0, r1, r2, r3, addr)                                     \
    asm volatile("ldmatrix.sync.aligned.m8n8.x4.shared.b16 {%0,%1,%2,%3}, [%4];" \
                 : "=r"(r0), "=r"(r1), "=r"(r2), "=r"(r3) : "r"(addr))

#define MMA_BF16(d, a0, a1, a2, a3, b0, b1)                                   \
    asm volatile("mma.sync.aligned.m16n8k16.row.col.f32.bf16.bf16.f32 "       \
                 "{%0,%1,%2,%3}, {%4,%5,%6,%7}, {%8,%9}, {%0,%1,%2,%3};"      \
                 : "+f"(d[0]), "+f"(d[1]), "+f"(d[2]), "+f"(d[3])             \
                 : "r"(a0), "r"(a1), "r"(a2), "r"(a3), "r"(b0), "r"(b1))

// ---------------- misc ----------------
__global__ void clear_i(int* p, int n) {
    for (int i = blockIdx.x * blockDim.x + threadIdx.x; i < n; i += gridDim.x * blockDim.x)
        p[i] = 0;
}

// ---------------- W fragment packing (bf16 hi/lo, mma order) ----------------
// One launch for all 4 layers. out float4 index (per layer):
// (ks*NT8 + n8)*32 + lane  ->  {bh0, bh1, bl0, bl1}
__global__ void wpack_all(const float* __restrict__ W0, const float* __restrict__ W1,
                          const float* __restrict__ W2, const float* __restrict__ W3,
                          float4* __restrict__ out) {
    int ks = blockIdx.x, n8 = blockIdx.y, layer = blockIdx.z;
    int lane = threadIdx.x;
    int M   = (layer < 3) ? 128 : 64;
    int NT8 = M / 8;
    if (n8 >= NT8) return;
    const float* W = (layer == 0) ? W0 : (layer == 1) ? W1 : (layer == 2) ? W2 : W3;

    int tc = lane & 3, g = lane >> 2;
    int n  = n8 * 8 + g;
    int k0 = ks * 16 + tc * 2;
    float w00 = __ldg(&W[(k0 + 0) * M + n]);
    float w01 = __ldg(&W[(k0 + 1) * M + n]);
    float w10 = __ldg(&W[(k0 + 8) * M + n]);
    float w11 = __ldg(&W[(k0 + 9) * M + n]);

    __nv_bfloat162 h0 = __float22bfloat162_rn(make_float2(w00, w01));
    __nv_bfloat162 h1 = __float22bfloat162_rn(make_float2(w10, w11));
    float2 f0 = __bfloat1622float2(h0);
    float2 f1 = __bfloat1622float2(h1);
    __nv_bfloat162 l0 = __float22bfloat162_rn(make_float2(w00 - f0.x, w01 - f0.y));
    __nv_bfloat162 l1 = __float22bfloat162_rn(make_float2(w10 - f1.x, w11 - f1.y));

    float4 v;
    v.x = __uint_as_float(*(unsigned*)&h0);
    v.y = __uint_as_float(*(unsigned*)&h1);
    v.z = __uint_as_float(*(unsigned*)&l0);
    v.w = __uint_as_float(*(unsigned*)&l1);
    out[(size_t)layer * 4096 + (ks * NT8 + n8) * 32 + lane] = v;
}

// ---------------- CSR build ----------------
__global__ void hist_k(const int* __restrict__ ei, int* __restrict__ deg, int E, int ET) {
    int e = blockIdx.x * blockDim.x + threadIdx.x;
    if (e >= ET) return;
    int d = (e < E) ? __ldg(&ei[E + e]) : (e - E);
    atomicAdd(&deg[d], 1);
}

__global__ void scan_k(const int* __restrict__ deg, int* __restrict__ roff,
                       int* __restrict__ cur) {
    __shared__ int ssum[1024];
    int tid = threadIdx.x;
    const int CH = (NN + 1023) / 1024;
    int base = tid * CH;
    int s = 0;
    for (int i = 0; i < CH; i++) {
        int n = base + i;
        if (n < NN) s += deg[n];
    }
    ssum[tid] = s;
    __syncthreads();
    for (int off = 1; off < 1024; off <<= 1) {
        int v = 0;
        if (tid >= off) v = ssum[tid - off];
        __syncthreads();
        if (tid >= off) ssum[tid] += v;
        __syncthreads();
    }
    int run = (tid == 0) ? 0 : ssum[tid - 1];
    for (int i = 0; i < CH; i++) {
        int n = base + i;
        if (n < NN) {
            roff[n] = run;
            cur[n]  = run;
            run += deg[n];
        }
    }
    if (tid == 1023) roff[NN] = ssum[1023];
}

__global__ void scatter_k(const int* __restrict__ ei, int* __restrict__ cur,
                          int* __restrict__ csrc, int E, int ET) {
    int e = blockIdx.x * blockDim.x + threadIdx.x;
    if (e >= ET) return;
    int s, d;
    if (e < E) { s = __ldg(&ei[e]); d = __ldg(&ei[E + e]); }
    else       { s = d = e - E; }
    int pos = atomicAdd(&cur[d], 1);
    csrc[pos] = s;
}

// ---------------- GEMM (3x bf16 mma.sync) + fused attention logits ----------
// C[rows, M] = act(A)[rows,128] @ W[128,M], fp32 accum via hi/lo bf16 split.
// Block: 128 threads (4 warps), 32 rows. Warp (wr,wc): rows wr*16+[0,16),
// cols wc*(M/2)+[0,M/2). A staged bf16 hi/lo in smem, fed by ldmatrix.
template <int M, bool BNIN, int H, int C>
__global__ __launch_bounds__(128, 6)
void gemm_attn_k(const float* __restrict__ A, const float4* __restrict__ wpack,
                 const float* __restrict__ bn,
                 const float* __restrict__ a_s, const float* __restrict__ a_d,
                 __nv_bfloat16* __restrict__ Cout, float* __restrict__ als,
                 float* __restrict__ ald, int rows) {
    const int NT8 = M / 8;        // total n8 tiles
    const int NW  = NT8 / 2;      // n8 tiles per warp
    const int LDA = 136;          // bf16 elems per A-stage row (128 + 8 pad)
    const int LD  = M + 4;        // fp32 epilogue stride

    __shared__ char smraw[17408];                 // max(2*32*136*2, 32*(M+4)*4)
    __nv_bfloat16* Ahi = (__nv_bfloat16*)smraw;   // [32][136]
    __nv_bfloat16* Alo = Ahi + 32 * LDA;
    float* hs = (float*)smraw;                    // reused after mainloop

    int t = threadIdx.x;
    int w = t >> 5, lane = t & 31;
    int wr = w >> 1, wc = w & 1;
    int row0 = blockIdx.x * 32;

    // ---- stage A (BN-ELU fused) as bf16 hi + lo residual ----
    for (int i = t; i < 32 * 32; i += 128) {
        int r = i >> 5, c4 = i & 31;
        float4 v = make_float4(0.f, 0.f, 0.f, 0.f);
        if (row0 + r < rows) {
            v = *(const float4*)&A[(size_t)(row0 + r) * 128 + c4 * 4];
            if (BNIN) {
                float4 sc = *(const float4*)&bn[2 * HD_ + c4 * 4];
                float4 sh = *(const float4*)&bn[3 * HD_ + c4 * 4];
                v.x = elu_f(v.x * sc.x + sh.x);
                v.y = elu_f(v.y * sc.y + sh.y);
                v.z = elu_f(v.z * sc.z + sh.z);
                v.w = elu_f(v.w * sc.w + sh.w);
            }
        }
        __nv_bfloat162 h0 = __float22bfloat162_rn(make_float2(v.x, v.y));
        __nv_bfloat162 h1 = __float22bfloat162_rn(make_float2(v.z, v.w));
        float2 f0 = __bfloat1622float2(h0);
        float2 f1 = __bfloat1622float2(h1);
        __nv_bfloat162 l0 = __float22bfloat162_rn(make_float2(v.x - f0.x, v.y - f0.y));
        __nv_bfloat162 l1 = __float22bfloat162_rn(make_float2(v.z - f1.x, v.w - f1.y));
        uint2 ph, pl;
        ph.x = *(unsigned*)&h0; ph.y = *(unsigned*)&h1;
        pl.x = *(unsigned*)&l0; pl.y = *(unsigned*)&l1;
        *(uint2*)&Ahi[r * LDA + c4 * 4] = ph;
        *(uint2*)&Alo[r * LDA + c4 * 4] = pl;
    }
    __syncthreads();

    float d[NW][4];
#pragma unroll
    for (int i = 0; i < NW; i++)
#pragma unroll
        for (int j = 0; j < 4; j++) d[i][j] = 0.f;

    int arow = wr * 16 + (lane & 15);
    int acolbase = (lane >> 4) << 3;
#pragma unroll
    for (int ks = 0; ks < 8; ks++) {
        unsigned a0, a1, a2, a3, q0, q1, q2, q3;
        unsigned hiaddr = smaddr(&Ahi[arow * LDA + ks * 16 + acolbase]);
        unsigned loaddr = smaddr(&Alo[arow * LDA + ks * 16 + acolbase]);
        LDMATRIX_X4(a0, a1, a2, a3, hiaddr);
        LDMATRIX_X4(q0, q1, q2, q3, loaddr);
        const float4* wp = wpack + (ks * NT8 + wc * NW) * 32 + lane;
#pragma unroll
        for (int i = 0; i < NW; i++) {
            float4 b = __ldg(&wp[i * 32]);
            unsigned bh0 = __float_as_uint(b.x), bh1 = __float_as_uint(b.y);
            unsigned bl0 = __float_as_uint(b.z), bl1 = __float_as_uint(b.w);
            MMA_BF16(d[i], a0, a1, a2, a3, bl0, bl1);  // hi * lo
            MMA_BF16(d[i], q0, q1, q2, q3, bh0, bh1);  // lo * hi
            MMA_BF16(d[i], a0, a1, a2, a3, bh0, bh1);  // hi * hi
        }
    }
    __syncthreads();   // done reading staged A; reuse smem as hs[32][M+4]

    // ---- epilogue: fragments -> smem fp32 tile ----
    {
        int g = lane >> 2, c0 = lane & 3;
#pragma unroll
        for (int i = 0; i < NW; i++) {
            int n8 = wc * NW + i;
            int col = n8 * 8 + c0 * 2;
            *(float2*)&hs[(wr * 16 + g) * LD + col]     = make_float2(d[i][0], d[i][1]);
            *(float2*)&hs[(wr * 16 + g + 8) * LD + col] = make_float2(d[i][2], d[i][3]);
        }
    }
    __syncthreads();

    // ---- Cout (bf16) coalesced from smem ----
    for (int i = t; i < 32 * (M / 4); i += 128) {
        int r = i / (M / 4), c4 = i % (M / 4);
        int gr = row0 + r;
        if (gr < rows) {
            float4 o = *(float4*)&hs[r * LD + c4 * 4];
            __nv_bfloat162 b0 = __float22bfloat162_rn(make_float2(o.x, o.y));
            __nv_bfloat162 b1 = __float22bfloat162_rn(make_float2(o.z, o.w));
            uint2 pk;
            pk.x = *(unsigned*)&b0;
            pk.y = *(unsigned*)&b1;
            *(uint2*)&Cout[(size_t)gr * M + c4 * 4] = pk;
        }
    }

    // ---- attention logits from smem (fp32, full precision) ----
    if (H == 4) {
        int row = t & 31, head = t >> 5;   // warp-uniform head
        const float4* hrow = (const float4*)&hs[row * LD + head * C];
        const float4* ap = (const float4*)(a_s + head * C);
        const float4* dp = (const float4*)(a_d + head * C);
        float s1 = 0.f, s2 = 0.f;
#pragma unroll
        for (int c4 = 0; c4 < C / 4; c4++) {
            float4 v = hrow[c4];
            float4 a = __ldg(&ap[c4]);
            float4 dd = __ldg(&dp[c4]);
            s1 += v.x * a.x + v.y * a.y + v.z * a.z + v.w * a.w;
            s2 += v.x * dd.x + v.y * dd.y + v.z * dd.z + v.w * dd.w;
        }
        int gr = row0 + row;
        if (gr < rows) {
            als[gr * 4 + head] = s1;
            ald[gr * 4 + head] = s2;
        }
    } else if (t < 64) {
        int row = t & 31, sel = t >> 5;
        const float4* av = (const float4*)(sel ? a_d : a_s);
        const float4* hrow = (const float4*)&hs[row * LD];
        float acc1 = 0.f;
#pragma unroll
        for (int c4 = 0; c4 < C / 4; c4++) {
            float4 v = hrow[c4];
            float4 a = __ldg(&av[c4]);
            acc1 += v.x * a.x + v.y * a.y + v.z * a.z + v.w * a.w;
        }
        int gr = row0 + row;
        if (gr < rows) {
            if (sel) ald[gr] = acc1; else als[gr] = acc1;
        }
    }
}

__device__ __forceinline__ float4 bf4_to_f4(uint2 pk) {
    __nv_bfloat162 b0 = *(__nv_bfloat162*)&pk.x;
    __nv_bfloat162 b1 = *(__nv_bfloat162*)&pk.y;
    float2 f0 = __bfloat1622float2(b0);
    float2 f1 = __bfloat1622float2(b1);
    return make_float4(f0.x, f0.y, f1.x, f1.y);
}
__device__ __forceinline__ float2 bf2_to_f2(unsigned pk) {
    __nv_bfloat162 b = *(__nv_bfloat162*)&pk;
    return __bfloat1622float2(b);
}

// ---------------- fused per-node GAT aggregation (warp per node) ------------
template <int H, int M, bool STATS, bool POOL>
__global__ void aggregate_k(const int* __restrict__ roff, const int* __restrict__ csrc,
                            const __nv_bfloat16* __restrict__ h,
                            const float* __restrict__ als,
                            const float* __restrict__ ald, const float* __restrict__ bias,
                            float* __restrict__ out, float* __restrict__ bn,
                            const int* __restrict__ bid, float* __restrict__ pool,
                            float* __restrict__ cnt) {
    __shared__ float sred[2 * HD_];
    __shared__ float4 sE[8 * 32];
    __shared__ int    sS[8 * 32];
    int t = threadIdx.x;
    if (STATS) {
        if (t < 2 * HD_) sred[t] = 0.f;
        __syncthreads();
    }
    int node = (blockIdx.x * blockDim.x + t) >> 5;
    int lane = t & 31;
    int w = t >> 5;
    bool active = (node < NN);
    int beg = 0, end = 0;
    if (active) { beg = roff[node]; end = roff[node + 1]; }

    float ad0 = 0.f, ad1 = 0.f, ad2 = 0.f, ad3 = 0.f;
    if (active) {
        if (H == 4) {
            float4 tt = *(const float4*)&ald[node * 4];
            ad0 = tt.x; ad1 = tt.y; ad2 = tt.z; ad3 = tt.w;
        } else {
            ad0 = ald[node];
        }
    }

    int jj = beg + lane;
    bool have = active && (jj < end);
    int sreg = 0;
    float s0 = 0.f, s1 = 0.f, s2 = 0.f, s3 = 0.f;
    if (have) {
        sreg = csrc[jj];
        float4 e;
        if (H == 4) {
            float4 a = *(const float4*)&als[sreg * 4];
            e.x = __expf(lrelu(a.x + ad0));
            e.y = __expf(lrelu(a.y + ad1));
            e.z = __expf(lrelu(a.z + ad2));
            e.w = __expf(lrelu(a.w + ad3));
            s0 += e.x; s1 += e.y; s2 += e.z; s3 += e.w;
        } else {
            e.x = __expf(lrelu(als[sreg] + ad0));
            e.y = e.z = e.w = 0.f;
            s0 += e.x;
        }
        sE[w * 32 + lane] = e;
        sS[w * 32 + lane] = sreg;
    }
    for (int j = jj + 32; j < end; j += 32) {
        int s = csrc[j];
        if (H == 4) {
            float4 a = *(const float4*)&als[s * 4];
            s0 += __expf(lrelu(a.x + ad0));
            s1 += __expf(lrelu(a.y + ad1));
            s2 += __expf(lrelu(a.z + ad2));
            s3 += __expf(lrelu(a.w + ad3));
        } else {
            s0 += __expf(lrelu(als[s] + ad0));
        }
    }
#pragma unroll
    for (int o = 16; o; o >>= 1) {
        s0 += __shfl_xor_sync(0xffffffffu, s0, o);
        if (H == 4) {
            s1 += __shfl_xor_sync(0xffffffffu, s1, o);
            s2 += __shfl_xor_sync(0xffffffffu, s2, o);
            s3 += __shfl_xor_sync(0xffffffffu, s3, o);
        }
    }
    __syncwarp();

    int cnt_e = end - beg;
    int cached = cnt_e < 32 ? cnt_e : 32;

    if (H == 4) {
        float r0 = 1.f / (s0 + 1e-16f), r1 = 1.f / (s1 + 1e-16f);
        float r2 = 1.f / (s2 + 1e-16f), r3 = 1.f / (s3 + 1e-16f);
        int head = lane >> 3;
        float rv  = lane < 16 ? (lane < 8 ? r0 : r1) : (lane < 24 ? r2 : r3);
        float adh = lane < 16 ? (lane < 8 ? ad0 : ad1) : (lane < 24 ? ad2 : ad3);

        float4 acc = make_float4(0.f, 0.f, 0.f, 0.f);
        const float* eb = (const float*)&sE[w * 32];
        const int*   sb = &sS[w * 32];
        int j2 = 0;
        for (; j2 + 4 <= cached; j2 += 4) {
            int sA = sb[j2], sB = sb[j2 + 1], sC = sb[j2 + 2], sD = sb[j2 + 3];
            float evA = eb[(j2 + 0) * 4 + head];
            float evB = eb[(j2 + 1) * 4 + head];
            float evC = eb[(j2 + 2) * 4 + head];
            float evD = eb[(j2 + 3) * 4 + head];
            uint2 pA = *(const uint2*)&h[(size_t)sA * 128 + lane * 4];
            uint2 pB = *(const uint2*)&h[(size_t)sB * 128 + lane * 4];
            uint2 pC = *(const uint2*)&h[(size_t)sC * 128 + lane * 4];
            uint2 pD = *(const uint2*)&h[(size_t)sD * 128 + lane * 4];
            float4 hA = bf4_to_f4(pA), hB = bf4_to_f4(pB);
            float4 hC = bf4_to_f4(pC), hD = bf4_to_f4(pD);
            acc.x += hA.x * evA + hB.x * evB + hC.x * evC + hD.x * evD;
            acc.y += hA.y * evA + hB.y * evB + hC.y * evC + hD.y * evD;
            acc.z += hA.z * evA + hB.z * evB + hC.z * evC + hD.z * evD;
            acc.w += hA.w * evA + hB.w * evB + hC.w * evC + hD.w * evD;
        }
        for (; j2 < cached; j2++) {
            int sA = sb[j2];
            float evA = eb[j2 * 4 + head];
            float4 hA = bf4_to_f4(*(const uint2*)&h[(size_t)sA * 128 + lane * 4]);
            acc.x += hA.x * evA; acc.y += hA.y * evA;
            acc.z += hA.z * evA; acc.w += hA.w * evA;
        }
        for (int j = beg + 32; j < end; j++) {
            int s = csrc[j];
            float4 a = *(const float4*)&als[s * 4];
            float ah = lane < 16 ? (lane < 8 ? a.x : a.y) : (lane < 24 ? a.z : a.w);
            float ev = __expf(lrelu(ah + adh));
            float4 hv = bf4_to_f4(*(const uint2*)&h[(size_t)s * 128 + lane * 4]);
            acc.x += hv.x * ev; acc.y += hv.y * ev;
            acc.z += hv.z * ev; acc.w += hv.w * ev;
        }
        float4 bi = active ? *(const float4*)&bias[lane * 4]
                           : make_float4(0.f, 0.f, 0.f, 0.f);
        float4 ov;
        ov.x = acc.x * rv + bi.x;
        ov.y = acc.y * rv + bi.y;
        ov.z = acc.z * rv + bi.z;
        ov.w = acc.w * rv + bi.w;
        if (active) *(float4*)&out[(size_t)node * 128 + lane * 4] = ov;

        if (STATS) {
            if (active) {
                int ch = lane * 4;
                atomicAdd(&sred[ch + 0], ov.x);
                atomicAdd(&sred[ch + 1], ov.y);
                atomicAdd(&sred[ch + 2], ov.z);
                atomicAdd(&sred[ch + 3], ov.w);
                atomicAdd(&sred[HD_ + ch + 0], ov.x * ov.x);
                atomicAdd(&sred[HD_ + ch + 1], ov.y * ov.y);
                atomicAdd(&sred[HD_ + ch + 2], ov.z * ov.z);
                atomicAdd(&sred[HD_ + ch + 3], ov.w * ov.w);
            }
            __syncthreads();
            if (t < 2 * HD_) atomicAdd(&bn[t], sred[t]);
        }
    } else {
        float r0 = 1.f / (s0 + 1e-16f);
        float2 acc = make_float2(0.f, 0.f);
        const float* eb = (const float*)&sE[w * 32];
        const int*   sb = &sS[w * 32];
        int j2 = 0;
        for (; j2 + 4 <= cached; j2 += 4) {
            int sA = sb[j2], sB = sb[j2 + 1], sC = sb[j2 + 2], sD = sb[j2 + 3];
            float eA = eb[(j2 + 0) * 4];
            float eB = eb[(j2 + 1) * 4];
            float eC = eb[(j2 + 2) * 4];
            float eD = eb[(j2 + 3) * 4];
            float2 hA = bf2_to_f2(*(const unsigned*)&h[(size_t)sA * 64 + lane * 2]);
            float2 hB = bf2_to_f2(*(const unsigned*)&h[(size_t)sB * 64 + lane * 2]);
            float2 hC = bf2_to_f2(*(const unsigned*)&h[(size_t)sC * 64 + lane * 2]);
            float2 hD = bf2_to_f2(*(const unsigned*)&h[(size_t)sD * 64 + lane * 2]);
            acc.x += hA.x * eA + hB.x * eB + hC.x * eC + hD.x * eD;
            acc.y += hA.y * eA + hB.y * eB + hC.y * eC + hD.y * eD;
        }
        for (; j2 < cached; j2++) {
            int sA = sb[j2];
            float eA = eb[j2 * 4];
            float2 hA = bf2_to_f2(*(const unsigned*)&h[(size_t)sA * 64 + lane * 2]);
            acc.x += hA.x * eA;
            acc.y += hA.y * eA;
        }
        for (int j = beg + 32; j < end; j++) {
            int s = csrc[j];
            float ev = __expf(lrelu(als[s] + ad0));
            float2 hv = bf2_to_f2(*(const unsigned*)&h[(size_t)s * 64 + lane * 2]);
            acc.x += hv.x * ev;
            acc.y += hv.y * ev;
        }
        if (active) {
            float2 bi = *(const float2*)&bias[lane * 2];
            float2 ov;
            ov.x = acc.x * r0 + bi.x;
            ov.y = acc.y * r0 + bi.y;
            *(float2*)&out[(size_t)node * 64 + lane * 2] = ov;
            if (POOL) {
                int g = __ldg(&bid[node]);          // warp-uniform
                atomicAdd(&pool[g * OUTC + lane * 2],     ov.x);
                atomicAdd(&pool[g * OUTC + lane * 2 + 1], ov.y);
                if (lane == 0) atomicAdd(&cnt[g], 1.f);
            }
        }
    }
}

// ---------------- BN finalize (self-clearing; optionally clears pool) -------
__global__ void bn_finalize(float* __restrict__ bn, const float* __restrict__ g,
                            const float* __restrict__ be, float* __restrict__ pool,
                            float* __restrict__ cnt, int clearPool) {
    int j = threadIdx.x;
    float mu = bn[j] / (float)NN;
    float var = bn[HD_ + j] / (float)NN - mu * mu;
    float sc = __ldg(&g[j]) * rsqrtf(var + 1e-5f);
    bn[2 * HD_ + j] = sc;
    bn[3 * HD_ + j] = __ldg(&be[j]) - mu * sc;
    bn[j] = 0.f;
    bn[HD_ + j] = 0.f;
    if (clearPool) {
        for (int i = j; i < NGRP * OUTC; i += HD_) pool[i] = 0.f;
        if (j < NGRP) cnt[j] = 0.f;
    }
}

__global__ void pool_fin(const float* __restrict__ pool, const float* __restrict__ cnt,
                         float* __restrict__ out) {
    int i = blockIdx.x * blockDim.x + threadIdx.x;
    if (i >= NGRP * OUTC) return;
    float c = cnt[i >> 6];
    out[i] = pool[i] / fmaxf(c, 1.f);
}

// ---------------- host ----------------
extern "C" void kernel_launch(void* const* d_in, const int* in_sizes, int n_in,
                              void* d_out, int out_size) {
    const float* x   = (const float*)d_in[0];
    const int*   ei  = (const int*)d_in[1];
    const int*   bid = (const int*)d_in[2];
    const float *W[4], *As[4], *Ad[4], *B[4];
    for (int i = 0; i < 4; i++) {
        W[i]  = (const float*)d_in[3 + 4 * i];
        As[i] = (const float*)d_in[4 + 4 * i];
        Ad[i] = (const float*)d_in[5 + 4 * i];
        B[i]  = (const float*)d_in[6 + 4 * i];
    }
    const float *G[3], *Be[3];
    for (int i = 0; i < 3; i++) {
        G[i]  = (const float*)d_in[19 + 2 * i];
        Be[i] = (const float*)d_in[20 + 2 * i];
    }
    int E  = in_sizes[1] / 2;
    int ET = E + NN;

    __nv_bfloat16* h_;
    float *agg_, *als_, *ald_, *bn_, *pool_, *cnt_;
    float4* wp_;
    int *deg_, *roff_, *cur_, *csrc_;
    cudaGetSymbolAddress((void**)&h_,    g_h);
    cudaGetSymbolAddress((void**)&agg_,  g_agg);
    cudaGetSymbolAddress((void**)&als_,  g_als);
    cudaGetSymbolAddress((void**)&ald_,  g_ald);
    cudaGetSymbolAddress((void**)&deg_,  g_deg);
    cudaGetSymbolAddress((void**)&roff_, g_roff);
    cudaGetSymbolAddress((void**)&cur_,  g_cur);
    cudaGetSymbolAddress((void**)&csrc_, g_csrc);
    cudaGetSymbolAddress((void**)&bn_,   g_bn);
    cudaGetSymbolAddress((void**)&pool_, g_pool);
    cudaGetSymbolAddress((void**)&cnt_,  g_cnt);
    cudaGetSymbolAddress((void**)&wp_,   g_wpack);

    const int TB = 256;
    const int AGG_BLOCKS = ceil_div(NN * 32, TB);
    const int GB = ceil_div(NN, 32);
    const int EB = ceil_div(ET, TB);

    // ---- W packing (independent) + CSR build + layer-0 GEMM ----
    wpack_all<<<dim3(8, 16, 4), 32>>>(W[0], W[1], W[2], W[3], wp_);
    clear_i<<<128, TB>>>(deg_, NN);
    hist_k<<<EB, TB>>>(ei, deg_, E, ET);
    scan_k<<<1, 1024>>>(deg_, roff_, cur_);
    gemm_attn_k<128, false, 4, 32><<<GB, 128>>>(x, wp_, bn_, As[0], Ad[0],
                                                h_, als_, ald_, NN);
    scatter_k<<<EB, TB>>>(ei, cur_, csrc_, E, ET);

    // ---- layer 0 aggregation ----
    aggregate_k<4, 128, true, false><<<AGG_BLOCKS, TB>>>(roff_, csrc_, h_, als_, ald_,
                                                         B[0], agg_, bn_, bid, pool_, cnt_);
    bn_finalize<<<1, HD_>>>(bn_, G[0], Be[0], pool_, cnt_, 0);

    // ---- layers 1,2 ----
    for (int l = 1; l < 3; l++) {
        gemm_attn_k<128, true, 4, 32><<<GB, 128>>>(agg_, wp_ + (size_t)l * 4096, bn_,
                                                   As[l], Ad[l], h_, als_, ald_, NN);
        aggregate_k<4, 128, true, false><<<AGG_BLOCKS, TB>>>(roff_, csrc_, h_, als_, ald_,
                                                             B[l], agg_, bn_, bid, pool_, cnt_);
        bn_finalize<<<1, HD_>>>(bn_, G[l], Be[l], pool_, cnt_, l == 2);
    }

    // ---- layer 3 (H=1, OUT=64) with fused pool accumulation ----
    gemm_attn_k<64, true, 1, 64><<<GB, 128>>>(agg_, wp_ + (size_t)3 * 4096, bn_,
                                              As[3], Ad[3], h_, als_, ald_, NN);
    aggregate_k<1, 64, false, true><<<AGG_BLOCKS, TB>>>(roff_, csrc_, h_, als_, ald_,
                                                        B[3], agg_, bn_, bid, pool_, cnt_);

    pool_fin<<<ceil_div(NGRP * OUTC, TB), TB>>>(pool_, cnt_, (float*)d_out);
}

// round 14
// speedup vs baseline: 1.6990x; 1.1820x over previous
#include <cuda_runtime.h>
#include <cuda_bf16.h>
#include <cstdint>

#define NN     50000
#define HD_    128
#define EMAX   800000
#define ETMAX  (EMAX + NN)
#define NGRP   64
#define OUTC   64
#define SB     256                       // scan block size
#define NBLK   ((NN + SB - 1) / SB)      // 196

// ---------------- scratch ----------------
__device__ __nv_bfloat16 g_h[NN * HD_];   // bf16 message payload
__device__ float  g_agg[NN * HD_];
__device__ float  g_als[NN * 4];
__device__ float  g_ald[NN * 4];
__device__ int    g_deg[NN];
__device__ int    g_roff[NN + 1];
__device__ int    g_cur[NN];
__device__ int    g_csrc[ETMAX];
__device__ int    g_bsum[NBLK];
__device__ float  g_bn[4 * HD_];   // sum | sumsq | scale | shift
__device__ float  g_pool[NGRP * OUTC];
__device__ float  g_cnt[NGRP];
__device__ float  g_wpack[4 * 16384];   // per-layer fragment-packed W (bf16 hi/lo)

static inline int ceil_div(int a, int b) { return (a + b - 1) / b; }

__device__ __forceinline__ float lrelu(float v) { return v > 0.f ? v : 0.2f * v; }
__device__ __forceinline__ float elu_f(float y) { return y > 0.f ? y : __expf(y) - 1.f; }

__device__ __forceinline__ unsigned smaddr(const void* p) {
    return (unsigned)__cvta_generic_to_shared(p);
}

#define LDMATRIX_X4(r0, r1, r2, r3, addr)                                     \
    asm volatile("ldmatrix.sync.aligned.m8n8.x4.shared.b16 {%0,%1,%2,%3}, [%4];" \
                 : "=r"(r0), "=r"(r1), "=r"(r2), "=r"(r3) : "r"(addr))

#define MMA_BF16(d, a0, a1, a2, a3, b0, b1)                                   \
    asm volatile("mma.sync.aligned.m16n8k16.row.col.f32.bf16.bf16.f32 "       \
                 "{%0,%1,%2,%3}, {%4,%5,%6,%7}, {%8,%9}, {%0,%1,%2,%3};"      \
                 : "+f"(d[0]), "+f"(d[1]), "+f"(d[2]), "+f"(d[3])             \
                 : "r"(a0), "r"(a1), "r"(a2), "r"(a3), "r"(b0), "r"(b1))

// ---------------- misc ----------------
__global__ void clear_i(int* p, int n) {
    for (int i = blockIdx.x * blockDim.x + threadIdx.x; i < n; i += gridDim.x * blockDim.x)
        p[i] = 0;
}

// ---------------- W fragment packing (bf16 hi/lo, mma order) ----------------
__global__ void wpack_all(const float* __restrict__ W0, const float* __restrict__ W1,
                          const float* __restrict__ W2, const float* __restrict__ W3,
                          float4* __restrict__ out) {
    int ks = blockIdx.x, n8 = blockIdx.y, layer = blockIdx.z;
    int lane = threadIdx.x;
    int M   = (layer < 3) ? 128 : 64;
    int NT8 = M / 8;
    if (n8 >= NT8) return;
    const float* W = (layer == 0) ? W0 : (layer == 1) ? W1 : (layer == 2) ? W2 : W3;

    int tc = lane & 3, g = lane >> 2;
    int n  = n8 * 8 + g;
    int k0 = ks * 16 + tc * 2;
    float w00 = __ldg(&W[(k0 + 0) * M + n]);
    float w01 = __ldg(&W[(k0 + 1) * M + n]);
    float w10 = __ldg(&W[(k0 + 8) * M + n]);
    float w11 = __ldg(&W[(k0 + 9) * M + n]);

    __nv_bfloat162 h0 = __float22bfloat162_rn(make_float2(w00, w01));
    __nv_bfloat162 h1 = __float22bfloat162_rn(make_float2(w10, w11));
    float2 f0 = __bfloat1622float2(h0);
    float2 f1 = __bfloat1622float2(h1);
    __nv_bfloat162 l0 = __float22bfloat162_rn(make_float2(w00 - f0.x, w01 - f0.y));
    __nv_bfloat162 l1 = __float22bfloat162_rn(make_float2(w10 - f1.x, w11 - f1.y));

    float4 v;
    v.x = __uint_as_float(*(unsigned*)&h0);
    v.y = __uint_as_float(*(unsigned*)&h1);
    v.z = __uint_as_float(*(unsigned*)&l0);
    v.w = __uint_as_float(*(unsigned*)&l1);
    out[(size_t)layer * 4096 + (ks * NT8 + n8) * 32 + lane] = v;
}

// ---------------- CSR build ----------------
__global__ void hist_k(const int* __restrict__ ei, int* __restrict__ deg, int E, int ET) {
    int e = blockIdx.x * blockDim.x + threadIdx.x;
    if (e >= ET) return;
    int d = (e < E) ? __ldg(&ei[E + e]) : (e - E);
    atomicAdd(&deg[d], 1);
}

// ---- 3-phase parallel exclusive scan over deg[NN] ----
__global__ void scan1_k(const int* __restrict__ deg, int* __restrict__ bsum) {
    __shared__ int ws[8];
    int i = blockIdx.x * SB + threadIdx.x;
    int v = (i < NN) ? deg[i] : 0;
#pragma unroll
    for (int o = 16; o; o >>= 1) v += __shfl_xor_sync(0xffffffffu, v, o);
    if ((threadIdx.x & 31) == 0) ws[threadIdx.x >> 5] = v;
    __syncthreads();
    if (threadIdx.x < 8) {
        int s = ws[threadIdx.x];
#pragma unroll
        for (int o = 4; o; o >>= 1) s += __shfl_xor_sync(0xffu, s, o);
        if (threadIdx.x == 0) bsum[blockIdx.x] = s;
    }
}

__global__ void scan2_k(int* __restrict__ bsum, int* __restrict__ roff) {
    // single block of 256 threads, NBLK <= 256: exclusive scan of bsum in place
    __shared__ int ws[8];
    int tid = threadIdx.x;
    int v = (tid < NBLK) ? bsum[tid] : 0;
    int lane = tid & 31, w = tid >> 5;
    int x = v;
#pragma unroll
    for (int o = 1; o < 32; o <<= 1) {
        int y = __shfl_up_sync(0xffffffffu, x, o);
        if (lane >= o) x += y;
    }
    if (lane == 31) ws[w] = x;
    __syncthreads();
    if (tid < 8) {
        int s = ws[tid];
#pragma unroll
        for (int o = 1; o < 8; o <<= 1) {
            int y = __shfl_up_sync(0xffu, s, o);
            if (tid >= o) s += y;
        }
        ws[tid] = s;
    }
    __syncthreads();
    int incl = x + (w > 0 ? ws[w - 1] : 0);
    if (tid < NBLK) bsum[tid] = incl - v;   // exclusive
    if (tid == 255) roff[NN] = incl;        // total (last thread has grand total)
}

__global__ void scan3_k(const int* __restrict__ deg, const int* __restrict__ bsum,
                        int* __restrict__ roff, int* __restrict__ cur) {
    __shared__ int ws[8];
    int i = blockIdx.x * SB + threadIdx.x;
    int v = (i < NN) ? deg[i] : 0;
    int lane = threadIdx.x & 31, w = threadIdx.x >> 5;
    int x = v;
#pragma unroll
    for (int o = 1; o < 32; o <<= 1) {
        int y = __shfl_up_sync(0xffffffffu, x, o);
        if (lane >= o) x += y;
    }
    if (lane == 31) ws[w] = x;
    __syncthreads();
    if (threadIdx.x < 8) {
        int s = ws[threadIdx.x];
#pragma unroll
        for (int o = 1; o < 8; o <<= 1) {
            int y = __shfl_up_sync(0xffu, s, o);
            if (threadIdx.x >= o) s += y;
        }
        ws[threadIdx.x] = s;
    }
    __syncthreads();
    int off = bsum[blockIdx.x] + x - v + (w > 0 ? ws[w - 1] : 0);
    if (i < NN) {
        roff[i] = off;
        cur[i]  = off;
    }
}

__global__ void scatter_k(const int* __restrict__ ei, int* __restrict__ cur,
                          int* __restrict__ csrc, int E, int ET) {
    int e = blockIdx.x * blockDim.x + threadIdx.x;
    if (e >= ET) return;
    int s, d;
    if (e < E) { s = __ldg(&ei[e]); d = __ldg(&ei[E + e]); }
    else       { s = d = e - E; }
    int pos = atomicAdd(&cur[d], 1);
    csrc[pos] = s;
}

// ---------------- GEMM (3x bf16 mma.sync) + fused attention logits ----------
template <int M, bool BNIN, int H, int C>
__global__ __launch_bounds__(128, 6)
void gemm_attn_k(const float* __restrict__ A, const float4* __restrict__ wpack,
                 const float* __restrict__ bn,
                 const float* __restrict__ a_s, const float* __restrict__ a_d,
                 __nv_bfloat16* __restrict__ Cout, float* __restrict__ als,
                 float* __restrict__ ald, int rows) {
    const int NT8 = M / 8;
    const int NW  = NT8 / 2;
    const int LDA = 136;
    const int LD  = M + 4;

    __shared__ char smraw[17408];
    __nv_bfloat16* Ahi = (__nv_bfloat16*)smraw;
    __nv_bfloat16* Alo = Ahi + 32 * LDA;
    float* hs = (float*)smraw;

    int t = threadIdx.x;
    int w = t >> 5, lane = t & 31;
    int wr = w >> 1, wc = w & 1;
    int row0 = blockIdx.x * 32;

    for (int i = t; i < 32 * 32; i += 128) {
        int r = i >> 5, c4 = i & 31;
        float4 v = make_float4(0.f, 0.f, 0.f, 0.f);
        if (row0 + r < rows) {
            v = *(const float4*)&A[(size_t)(row0 + r) * 128 + c4 * 4];
            if (BNIN) {
                float4 sc = *(const float4*)&bn[2 * HD_ + c4 * 4];
                float4 sh = *(const float4*)&bn[3 * HD_ + c4 * 4];
                v.x = elu_f(v.x * sc.x + sh.x);
                v.y = elu_f(v.y * sc.y + sh.y);
                v.z = elu_f(v.z * sc.z + sh.z);
                v.w = elu_f(v.w * sc.w + sh.w);
            }
        }
        __nv_bfloat162 h0 = __float22bfloat162_rn(make_float2(v.x, v.y));
        __nv_bfloat162 h1 = __float22bfloat162_rn(make_float2(v.z, v.w));
        float2 f0 = __bfloat1622float2(h0);
        float2 f1 = __bfloat1622float2(h1);
        __nv_bfloat162 l0 = __float22bfloat162_rn(make_float2(v.x - f0.x, v.y - f0.y));
        __nv_bfloat162 l1 = __float22bfloat162_rn(make_float2(v.z - f1.x, v.w - f1.y));
        uint2 ph, pl;
        ph.x = *(unsigned*)&h0; ph.y = *(unsigned*)&h1;
        pl.x = *(unsigned*)&l0; pl.y = *(unsigned*)&l1;
        *(uint2*)&Ahi[r * LDA + c4 * 4] = ph;
        *(uint2*)&Alo[r * LDA + c4 * 4] = pl;
    }
    __syncthreads();

    float d[NW][4];
#pragma unroll
    for (int i = 0; i < NW; i++)
#pragma unroll
        for (int j = 0; j < 4; j++) d[i][j] = 0.f;

    int arow = wr * 16 + (lane & 15);
    int acolbase = (lane >> 4) << 3;
#pragma unroll
    for (int ks = 0; ks < 8; ks++) {
        unsigned a0, a1, a2, a3, q0, q1, q2, q3;
        unsigned hiaddr = smaddr(&Ahi[arow * LDA + ks * 16 + acolbase]);
        unsigned loaddr = smaddr(&Alo[arow * LDA + ks * 16 + acolbase]);
        LDMATRIX_X4(a0, a1, a2, a3, hiaddr);
        LDMATRIX_X4(q0, q1, q2, q3, loaddr);
        const float4* wp = wpack + (ks * NT8 + wc * NW) * 32 + lane;
#pragma unroll
        for (int i = 0; i < NW; i++) {
            float4 b = __ldg(&wp[i * 32]);
            unsigned bh0 = __float_as_uint(b.x), bh1 = __float_as_uint(b.y);
            unsigned bl0 = __float_as_uint(b.z), bl1 = __float_as_uint(b.w);
            MMA_BF16(d[i], a0, a1, a2, a3, bl0, bl1);
            MMA_BF16(d[i], q0, q1, q2, q3, bh0, bh1);
            MMA_BF16(d[i], a0, a1, a2, a3, bh0, bh1);
        }
    }
    __syncthreads();

    {
        int g = lane >> 2, c0 = lane & 3;
#pragma unroll
        for (int i = 0; i < NW; i++) {
            int n8 = wc * NW + i;
            int col = n8 * 8 + c0 * 2;
            *(float2*)&hs[(wr * 16 + g) * LD + col]     = make_float2(d[i][0], d[i][1]);
            *(float2*)&hs[(wr * 16 + g + 8) * LD + col] = make_float2(d[i][2], d[i][3]);
        }
    }
    __syncthreads();

    for (int i = t; i < 32 * (M / 4); i += 128) {
        int r = i / (M / 4), c4 = i % (M / 4);
        int gr = row0 + r;
        if (gr < rows) {
            float4 o = *(float4*)&hs[r * LD + c4 * 4];
            __nv_bfloat162 b0 = __float22bfloat162_rn(make_float2(o.x, o.y));
            __nv_bfloat162 b1 = __float22bfloat162_rn(make_float2(o.z, o.w));
            uint2 pk;
            pk.x = *(unsigned*)&b0;
            pk.y = *(unsigned*)&b1;
            *(uint2*)&Cout[(size_t)gr * M + c4 * 4] = pk;
        }
    }

    if (H == 4) {
        int row = t & 31, head = t >> 5;
        const float4* hrow = (const float4*)&hs[row * LD + head * C];
        const float4* ap = (const float4*)(a_s + head * C);
        const float4* dp = (const float4*)(a_d + head * C);
        float s1 = 0.f, s2 = 0.f;
#pragma unroll
        for (int c4 = 0; c4 < C / 4; c4++) {
            float4 v = hrow[c4];
            float4 a = __ldg(&ap[c4]);
            float4 dd = __ldg(&dp[c4]);
            s1 += v.x * a.x + v.y * a.y + v.z * a.z + v.w * a.w;
            s2 += v.x * dd.x + v.y * dd.y + v.z * dd.z + v.w * dd.w;
        }
        int gr = row0 + row;
        if (gr < rows) {
            als[gr * 4 + head] = s1;
            ald[gr * 4 + head] = s2;
        }
    } else if (t < 64) {
        int row = t & 31, sel = t >> 5;
        const float4* av = (const float4*)(sel ? a_d : a_s);
        const float4* hrow = (const float4*)&hs[row * LD];
        float acc1 = 0.f;
#pragma unroll
        for (int c4 = 0; c4 < C / 4; c4++) {
            float4 v = hrow[c4];
            float4 a = __ldg(&av[c4]);
            acc1 += v.x * a.x + v.y * a.y + v.z * a.z + v.w * a.w;
        }
        int gr = row0 + row;
        if (gr < rows) {
            if (sel) ald[gr] = acc1; else als[gr] = acc1;
        }
    }
}

__device__ __forceinline__ float4 bf4_to_f4(uint2 pk) {
    __nv_bfloat162 b0 = *(__nv_bfloat162*)&pk.x;
    __nv_bfloat162 b1 = *(__nv_bfloat162*)&pk.y;
    float2 f0 = __bfloat1622float2(b0);
    float2 f1 = __bfloat1622float2(b1);
    return make_float4(f0.x, f0.y, f1.x, f1.y);
}
__device__ __forceinline__ float2 bf2_to_f2(unsigned pk) {
    __nv_bfloat162 b = *(__nv_bfloat162*)&pk;
    return __bfloat1622float2(b);
}

// ---------------- fused per-node GAT aggregation (warp per node) ------------
template <int H, int M, bool STATS, bool POOL>
__global__ void aggregate_k(const int* __restrict__ roff, const int* __restrict__ csrc,
                            const __nv_bfloat16* __restrict__ h,
                            const float* __restrict__ als,
                            const float* __restrict__ ald, const float* __restrict__ bias,
                            float* __restrict__ out, float* __restrict__ bn,
                            const int* __restrict__ bid, float* __restrict__ pool,
                            float* __restrict__ cnt) {
    __shared__ float sred[2 * HD_];
    __shared__ float4 sE[8 * 32];
    __shared__ int    sS[8 * 32];
    int t = threadIdx.x;
    if (STATS) {
        if (t < 2 * HD_) sred[t] = 0.f;
        __syncthreads();
    }
    int node = (blockIdx.x * blockDim.x + t) >> 5;
    int lane = t & 31;
    int w = t >> 5;
    bool active = (node < NN);
    int beg = 0, end = 0;
    if (active) { beg = roff[node]; end = roff[node + 1]; }

    float ad0 = 0.f, ad1 = 0.f, ad2 = 0.f, ad3 = 0.f;
    if (active) {
        if (H == 4) {
            float4 tt = *(const float4*)&ald[node * 4];
            ad0 = tt.x; ad1 = tt.y; ad2 = tt.z; ad3 = tt.w;
        } else {
            ad0 = ald[node];
        }
    }

    int jj = beg + lane;
    bool have = active && (jj < end);
    int sreg = 0;
    float s0 = 0.f, s1 = 0.f, s2 = 0.f, s3 = 0.f;
    if (have) {
        sreg = csrc[jj];
        float4 e;
        if (H == 4) {
            float4 a = *(const float4*)&als[sreg * 4];
            e.x = __expf(lrelu(a.x + ad0));
            e.y = __expf(lrelu(a.y + ad1));
            e.z = __expf(lrelu(a.z + ad2));
            e.w = __expf(lrelu(a.w + ad3));
            s0 += e.x; s1 += e.y; s2 += e.z; s3 += e.w;
        } else {
            e.x = __expf(lrelu(als[sreg] + ad0));
            e.y = e.z = e.w = 0.f;
            s0 += e.x;
        }
        sE[w * 32 + lane] = e;
        sS[w * 32 + lane] = sreg;
    }
    for (int j = jj + 32; j < end; j += 32) {
        int s = csrc[j];
        if (H == 4) {
            float4 a = *(const float4*)&als[s * 4];
            s0 += __expf(lrelu(a.x + ad0));
            s1 += __expf(lrelu(a.y + ad1));
            s2 += __expf(lrelu(a.z + ad2));
            s3 += __expf(lrelu(a.w + ad3));
        } else {
            s0 += __expf(lrelu(als[s] + ad0));
        }
    }
#pragma unroll
    for (int o = 16; o; o >>= 1) {
        s0 += __shfl_xor_sync(0xffffffffu, s0, o);
        if (H == 4) {
            s1 += __shfl_xor_sync(0xffffffffu, s1, o);
            s2 += __shfl_xor_sync(0xffffffffu, s2, o);
            s3 += __shfl_xor_sync(0xffffffffu, s3, o);
        }
    }
    __syncwarp();

    int cnt_e = end - beg;
    int cached = cnt_e < 32 ? cnt_e : 32;

    if (H == 4) {
        float r0 = 1.f / (s0 + 1e-16f), r1 = 1.f / (s1 + 1e-16f);
        float r2 = 1.f / (s2 + 1e-16f), r3 = 1.f / (s3 + 1e-16f);
        int head = lane >> 3;
        float rv  = lane < 16 ? (lane < 8 ? r0 : r1) : (lane < 24 ? r2 : r3);
        float adh = lane < 16 ? (lane < 8 ? ad0 : ad1) : (lane < 24 ? ad2 : ad3);

        float4 acc = make_float4(0.f, 0.f, 0.f, 0.f);
        const float* eb = (const float*)&sE[w * 32];
        const int*   sb = &sS[w * 32];
        int j2 = 0;
        for (; j2 + 4 <= cached; j2 += 4) {
            int sA = sb[j2], sB = sb[j2 + 1], sC = sb[j2 + 2], sD = sb[j2 + 3];
            float evA = eb[(j2 + 0) * 4 + head];
            float evB = eb[(j2 + 1) * 4 + head];
            float evC = eb[(j2 + 2) * 4 + head];
            float evD = eb[(j2 + 3) * 4 + head];
            uint2 pA = *(const uint2*)&h[(size_t)sA * 128 + lane * 4];
            uint2 pB = *(const uint2*)&h[(size_t)sB * 128 + lane * 4];
            uint2 pC = *(const uint2*)&h[(size_t)sC * 128 + lane * 4];
            uint2 pD = *(const uint2*)&h[(size_t)sD * 128 + lane * 4];
            float4 hA = bf4_to_f4(pA), hB = bf4_to_f4(pB);
            float4 hC = bf4_to_f4(pC), hD = bf4_to_f4(pD);
            acc.x += hA.x * evA + hB.x * evB + hC.x * evC + hD.x * evD;
            acc.y += hA.y * evA + hB.y * evB + hC.y * evC + hD.y * evD;
            acc.z += hA.z * evA + hB.z * evB + hC.z * evC + hD.z * evD;
            acc.w += hA.w * evA + hB.w * evB + hC.w * evC + hD.w * evD;
        }
        for (; j2 < cached; j2++) {
            int sA = sb[j2];
            float evA = eb[j2 * 4 + head];
            float4 hA = bf4_to_f4(*(const uint2*)&h[(size_t)sA * 128 + lane * 4]);
            acc.x += hA.x * evA; acc.y += hA.y * evA;
            acc.z += hA.z * evA; acc.w += hA.w * evA;
        }
        for (int j = beg + 32; j < end; j++) {
            int s = csrc[j];
            float4 a = *(const float4*)&als[s * 4];
            float ah = lane < 16 ? (lane < 8 ? a.x : a.y) : (lane < 24 ? a.z : a.w);
            float ev = __expf(lrelu(ah + adh));
            float4 hv = bf4_to_f4(*(const uint2*)&h[(size_t)s * 128 + lane * 4]);
            acc.x += hv.x * ev; acc.y += hv.y * ev;
            acc.z += hv.z * ev; acc.w += hv.w * ev;
        }
        float4 bi = active ? *(const float4*)&bias[lane * 4]
                           : make_float4(0.f, 0.f, 0.f, 0.f);
        float4 ov;
        ov.x = acc.x * rv + bi.x;
        ov.y = acc.y * rv + bi.y;
        ov.z = acc.z * rv + bi.z;
        ov.w = acc.w * rv + bi.w;
        if (active) *(float4*)&out[(size_t)node * 128 + lane * 4] = ov;

        if (STATS) {
            if (active) {
                int ch = lane * 4;
                atomicAdd(&sred[ch + 0], ov.x);
                atomicAdd(&sred[ch + 1], ov.y);
                atomicAdd(&sred[ch + 2], ov.z);
                atomicAdd(&sred[ch + 3], ov.w);
                atomicAdd(&sred[HD_ + ch + 0], ov.x * ov.x);
                atomicAdd(&sred[HD_ + ch + 1], ov.y * ov.y);
                atomicAdd(&sred[HD_ + ch + 2], ov.z * ov.z);
                atomicAdd(&sred[HD_ + ch + 3], ov.w * ov.w);
            }
            __syncthreads();
            if (t < 2 * HD_) atomicAdd(&bn[t], sred[t]);
        }
    } else {
        float r0 = 1.f / (s0 + 1e-16f);
        float2 acc = make_float2(0.f, 0.f);
        const float* eb = (const float*)&sE[w * 32];
        const int*   sb = &sS[w * 32];
        int j2 = 0;
        for (; j2 + 4 <= cached; j2 += 4) {
            int sA = sb[j2], sB = sb[j2 + 1], sC = sb[j2 + 2], sD = sb[j2 + 3];
            float eA = eb[(j2 + 0) * 4];
            float eB = eb[(j2 + 1) * 4];
            float eC = eb[(j2 + 2) * 4];
            float eD = eb[(j2 + 3) * 4];
            float2 hA = bf2_to_f2(*(const unsigned*)&h[(size_t)sA * 64 + lane * 2]);
            float2 hB = bf2_to_f2(*(const unsigned*)&h[(size_t)sB * 64 + lane * 2]);
            float2 hC = bf2_to_f2(*(const unsigned*)&h[(size_t)sC * 64 + lane * 2]);
            float2 hD = bf2_to_f2(*(const unsigned*)&h[(size_t)sD * 64 + lane * 2]);
            acc.x += hA.x * eA + hB.x * eB + hC.x * eC + hD.x * eD;
            acc.y += hA.y * eA + hB.y * eB + hC.y * eC + hD.y * eD;
        }
        for (; j2 < cached; j2++) {
            int sA = sb[j2];
            float eA = eb[j2 * 4];
            float2 hA = bf2_to_f2(*(const unsigned*)&h[(size_t)sA * 64 + lane * 2]);
            acc.x += hA.x * eA;
            acc.y += hA.y * eA;
        }
        for (int j = beg + 32; j < end; j++) {
            int s = csrc[j];
            float ev = __expf(lrelu(als[s] + ad0));
            float2 hv = bf2_to_f2(*(const unsigned*)&h[(size_t)s * 64 + lane * 2]);
            acc.x += hv.x * ev;
            acc.y += hv.y * ev;
        }
        if (active) {
            float2 bi = *(const float2*)&bias[lane * 2];
            float2 ov;
            ov.x = acc.x * r0 + bi.x;
            ov.y = acc.y * r0 + bi.y;
            *(float2*)&out[(size_t)node * 64 + lane * 2] = ov;
            if (POOL) {
                int g = __ldg(&bid[node]);
                atomicAdd(&pool[g * OUTC + lane * 2],     ov.x);
                atomicAdd(&pool[g * OUTC + lane * 2 + 1], ov.y);
                if (lane == 0) atomicAdd(&cnt[g], 1.f);
            }
        }
    }
}

// ---------------- BN finalize (self-clearing; optionally clears pool) -------
__global__ void bn_finalize(float* __restrict__ bn, const float* __restrict__ g,
                            const float* __restrict__ be, float* __restrict__ pool,
                            float* __restrict__ cnt, int clearPool) {
    int j = threadIdx.x;
    float mu = bn[j] / (float)NN;
    float var = bn[HD_ + j] / (float)NN - mu * mu;
    float sc = __ldg(&g[j]) * rsqrtf(var + 1e-5f);
    bn[2 * HD_ + j] = sc;
    bn[3 * HD_ + j] = __ldg(&be[j]) - mu * sc;
    bn[j] = 0.f;
    bn[HD_ + j] = 0.f;
    if (clearPool) {
        for (int i = j; i < NGRP * OUTC; i += HD_) pool[i] = 0.f;
        if (j < NGRP) cnt[j] = 0.f;
    }
}

__global__ void pool_fin(const float* __restrict__ pool, const float* __restrict__ cnt,
                         float* __restrict__ out) {
    int i = blockIdx.x * blockDim.x + threadIdx.x;
    if (i >= NGRP * OUTC) return;
    float c = cnt[i >> 6];
    out[i] = pool[i] / fmaxf(c, 1.f);
}

// ---------------- host ----------------
extern "C" void kernel_launch(void* const* d_in, const int* in_sizes, int n_in,
                              void* d_out, int out_size) {
    const float* x   = (const float*)d_in[0];
    const int*   ei  = (const int*)d_in[1];
    const int*   bid = (const int*)d_in[2];
    const float *W[4], *As[4], *Ad[4], *B[4];
    for (int i = 0; i < 4; i++) {
        W[i]  = (const float*)d_in[3 + 4 * i];
        As[i] = (const float*)d_in[4 + 4 * i];
        Ad[i] = (const float*)d_in[5 + 4 * i];
        B[i]  = (const float*)d_in[6 + 4 * i];
    }
    const float *G[3], *Be[3];
    for (int i = 0; i < 3; i++) {
        G[i]  = (const float*)d_in[19 + 2 * i];
        Be[i] = (const float*)d_in[20 + 2 * i];
    }
    int E  = in_sizes[1] / 2;
    int ET = E + NN;

    __nv_bfloat16* h_;
    float *agg_, *als_, *ald_, *bn_, *pool_, *cnt_;
    float4* wp_;
    int *deg_, *roff_, *cur_, *csrc_, *bsum_;
    cudaGetSymbolAddress((void**)&h_,    g_h);
    cudaGetSymbolAddress((void**)&agg_,  g_agg);
    cudaGetSymbolAddress((void**)&als_,  g_als);
    cudaGetSymbolAddress((void**)&ald_,  g_ald);
    cudaGetSymbolAddress((void**)&deg_,  g_deg);
    cudaGetSymbolAddress((void**)&roff_, g_roff);
    cudaGetSymbolAddress((void**)&cur_,  g_cur);
    cudaGetSymbolAddress((void**)&csrc_, g_csrc);
    cudaGetSymbolAddress((void**)&bsum_, g_bsum);
    cudaGetSymbolAddress((void**)&bn_,   g_bn);
    cudaGetSymbolAddress((void**)&pool_, g_pool);
    cudaGetSymbolAddress((void**)&cnt_,  g_cnt);
    cudaGetSymbolAddress((void**)&wp_,   g_wpack);

    const int TB = 256;
    const int AGG_BLOCKS = ceil_div(NN * 32, TB);
    const int GB = ceil_div(NN, 32);
    const int EB = ceil_div(ET, TB);

    // ---- W packing + CSR build (parallel scan) + layer-0 GEMM ----
    wpack_all<<<dim3(8, 16, 4), 32>>>(W[0], W[1], W[2], W[3], wp_);
    clear_i<<<128, TB>>>(deg_, NN);
    hist_k<<<EB, TB>>>(ei, deg_, E, ET);
    scan1_k<<<NBLK, SB>>>(deg_, bsum_);
    scan2_k<<<1, 256>>>(bsum_, roff_);
    scan3_k<<<NBLK, SB>>>(deg_, bsum_, roff_, cur_);
    gemm_attn_k<128, false, 4, 32><<<GB, 128>>>(x, wp_, bn_, As[0], Ad[0],
                                                h_, als_, ald_, NN);
    scatter_k<<<EB, TB>>>(ei, cur_, csrc_, E, ET);

    // ---- layer 0 aggregation ----
    aggregate_k<4, 128, true, false><<<AGG_BLOCKS, TB>>>(roff_, csrc_, h_, als_, ald_,
                                                         B[0], agg_, bn_, bid, pool_, cnt_);
    bn_finalize<<<1, HD_>>>(bn_, G[0], Be[0], pool_, cnt_, 0);

    // ---- layers 1,2 ----
    for (int l = 1; l < 3; l++) {
        gemm_attn_k<128, true, 4, 32><<<GB, 128>>>(agg_, wp_ + (size_t)l * 4096, bn_,
                                                   As[l], Ad[l], h_, als_, ald_, NN);
        aggregate_k<4, 128, true, false><<<AGG_BLOCKS, TB>>>(roff_, csrc_, h_, als_, ald_,
                                                             B[l], agg_, bn_, bid, pool_, cnt_);
        bn_finalize<<<1, HD_>>>(bn_, G[l], Be[l], pool_, cnt_, l == 2);
    }

    // ---- layer 3 (H=1, OUT=64) with fused pool accumulation ----
    gemm_attn_k<64, true, 1, 64><<<GB, 128>>>(agg_, wp_ + (size_t)3 * 4096, bn_,
                                              As[3], Ad[3], h_, als_, ald_, NN);
    aggregate_k<1, 64, false, true><<<AGG_BLOCKS, TB>>>(roff_, csrc_, h_, als_, ald_,
                                                        B[3], agg_, bn_, bid, pool_, cnt_);

    pool_fin<<<ceil_div(NGRP * OUTC, TB), TB>>>(pool_, cnt_, (float*)d_out);
}

// round 15
// speedup vs baseline: 1.7687x; 1.0410x over previous
#include <cuda_runtime.h>
#include <cuda_bf16.h>
#include <cstdint>

#define NN     50000
#define HD_    128
#define EMAX   800000
#define ETMAX  (EMAX + NN)
#define NGRP   64
#define OUTC   64
#define SB     256
#define NBLK   ((NN + SB - 1) / SB)

// ---------------- scratch ----------------
__device__ __nv_bfloat16 g_h[NN * HD_];
__device__ float  g_agg[NN * HD_];
__device__ float  g_als[NN * 4];
__device__ float  g_ald[NN * 4];
__device__ int    g_deg[NN];
__device__ int    g_roff[NN + 1];
__device__ int    g_cur[NN];
__device__ int    g_csrc[ETMAX];
__device__ int    g_bsum[NBLK];
__device__ float  g_bn[4 * HD_];
__device__ float  g_pool[NGRP * OUTC];
__device__ float  g_cnt[NGRP];
__device__ float  g_wpack[4 * 16384];

static inline int ceil_div(int a, int b) { return (a + b - 1) / b; }

__device__ __forceinline__ float lrelu(float v) { return v > 0.f ? v : 0.2f * v; }
__device__ __forceinline__ float elu_f(float y) { return y > 0.f ? y : __expf(y) - 1.f; }

__device__ __forceinline__ unsigned smaddr(const void* p) {
    return (unsigned)__cvta_generic_to_shared(p);
}

#define LDMATRIX_X4(r0, r1, r2, r3, addr)                                     \
    asm volatile("ldmatrix.sync.aligned.m8n8.x4.shared.b16 {%0,%1,%2,%3}, [%4];" \
                 : "=r"(r0), "=r"(r1), "=r"(r2), "=r"(r3) : "r"(addr))

#define MMA_BF16(d, a0, a1, a2, a3, b0, b1)                                   \
    asm volatile("mma.sync.aligned.m16n8k16.row.col.f32.bf16.bf16.f32 "       \
                 "{%0,%1,%2,%3}, {%4,%5,%6,%7}, {%8,%9}, {%0,%1,%2,%3};"      \
                 : "+f"(d[0]), "+f"(d[1]), "+f"(d[2]), "+f"(d[3])             \
                 : "r"(a0), "r"(a1), "r"(a2), "r"(a3), "r"(b0), "r"(b1))

// ---------------- misc ----------------
__global__ void clear_i(int* p, int n) {
    for (int i = blockIdx.x * blockDim.x + threadIdx.x; i < n; i += gridDim.x * blockDim.x)
        p[i] = 0;
}

// ---------------- W fragment packing ----------------
__global__ void wpack_all(const float* __restrict__ W0, const float* __restrict__ W1,
                          const float* __restrict__ W2, const float* __restrict__ W3,
                          float4* __restrict__ out) {
    int ks = blockIdx.x, n8 = blockIdx.y, layer = blockIdx.z;
    int lane = threadIdx.x;
    int M   = (layer < 3) ? 128 : 64;
    int NT8 = M / 8;
    if (n8 >= NT8) return;
    const float* W = (layer == 0) ? W0 : (layer == 1) ? W1 : (layer == 2) ? W2 : W3;

    int tc = lane & 3, g = lane >> 2;
    int n  = n8 * 8 + g;
    int k0 = ks * 16 + tc * 2;
    float w00 = __ldg(&W[(k0 + 0) * M + n]);
    float w01 = __ldg(&W[(k0 + 1) * M + n]);
    float w10 = __ldg(&W[(k0 + 8) * M + n]);
    float w11 = __ldg(&W[(k0 + 9) * M + n]);

    __nv_bfloat162 h0 = __float22bfloat162_rn(make_float2(w00, w01));
    __nv_bfloat162 h1 = __float22bfloat162_rn(make_float2(w10, w11));
    float2 f0 = __bfloat1622float2(h0);
    float2 f1 = __bfloat1622float2(h1);
    __nv_bfloat162 l0 = __float22bfloat162_rn(make_float2(w00 - f0.x, w01 - f0.y));
    __nv_bfloat162 l1 = __float22bfloat162_rn(make_float2(w10 - f1.x, w11 - f1.y));

    float4 v;
    v.x = __uint_as_float(*(unsigned*)&h0);
    v.y = __uint_as_float(*(unsigned*)&h1);
    v.z = __uint_as_float(*(unsigned*)&l0);
    v.w = __uint_as_float(*(unsigned*)&l1);
    out[(size_t)layer * 4096 + (ks * NT8 + n8) * 32 + lane] = v;
}

// ---------------- CSR build ----------------
__global__ void hist_k(const int* __restrict__ ei, int* __restrict__ deg, int E, int ET) {
    int e = blockIdx.x * blockDim.x + threadIdx.x;
    if (e >= ET) return;
    int d = (e < E) ? __ldg(&ei[E + e]) : (e - E);
    atomicAdd(&deg[d], 1);
}

__global__ void scan1_k(const int* __restrict__ deg, int* __restrict__ bsum) {
    __shared__ int ws[8];
    int i = blockIdx.x * SB + threadIdx.x;
    int v = (i < NN) ? deg[i] : 0;
#pragma unroll
    for (int o = 16; o; o >>= 1) v += __shfl_xor_sync(0xffffffffu, v, o);
    if ((threadIdx.x & 31) == 0) ws[threadIdx.x >> 5] = v;
    __syncthreads();
    if (threadIdx.x < 8) {
        int s = ws[threadIdx.x];
#pragma unroll
        for (int o = 4; o; o >>= 1) s += __shfl_xor_sync(0xffu, s, o);
        if (threadIdx.x == 0) bsum[blockIdx.x] = s;
    }
}

__global__ void scan2_k(int* __restrict__ bsum, int* __restrict__ roff) {
    __shared__ int ws[8];
    int tid = threadIdx.x;
    int v = (tid < NBLK) ? bsum[tid] : 0;
    int lane = tid & 31, w = tid >> 5;
    int x = v;
#pragma unroll
    for (int o = 1; o < 32; o <<= 1) {
        int y = __shfl_up_sync(0xffffffffu, x, o);
        if (lane >= o) x += y;
    }
    if (lane == 31) ws[w] = x;
    __syncthreads();
    if (tid < 8) {
        int s = ws[tid];
#pragma unroll
        for (int o = 1; o < 8; o <<= 1) {
            int y = __shfl_up_sync(0xffu, s, o);
            if (tid >= o) s += y;
        }
        ws[tid] = s;
    }
    __syncthreads();
    int incl = x + (w > 0 ? ws[w - 1] : 0);
    if (tid < NBLK) bsum[tid] = incl - v;
    if (tid == 255) roff[NN] = incl;
}

__global__ void scan3_k(const int* __restrict__ deg, const int* __restrict__ bsum,
                        int* __restrict__ roff, int* __restrict__ cur) {
    __shared__ int ws[8];
    int i = blockIdx.x * SB + threadIdx.x;
    int v = (i < NN) ? deg[i] : 0;
    int lane = threadIdx.x & 31, w = threadIdx.x >> 5;
    int x = v;
#pragma unroll
    for (int o = 1; o < 32; o <<= 1) {
        int y = __shfl_up_sync(0xffffffffu, x, o);
        if (lane >= o) x += y;
    }
    if (lane == 31) ws[w] = x;
    __syncthreads();
    if (threadIdx.x < 8) {
        int s = ws[threadIdx.x];
#pragma unroll
        for (int o = 1; o < 8; o <<= 1) {
            int y = __shfl_up_sync(0xffu, s, o);
            if (threadIdx.x >= o) s += y;
        }
        ws[threadIdx.x] = s;
    }
    __syncthreads();
    int off = bsum[blockIdx.x] + x - v + (w > 0 ? ws[w - 1] : 0);
    if (i < NN) {
        roff[i] = off;
        cur[i]  = off;
    }
}

__global__ void scatter_k(const int* __restrict__ ei, int* __restrict__ cur,
                          int* __restrict__ csrc, int E, int ET) {
    int e = blockIdx.x * blockDim.x + threadIdx.x;
    if (e >= ET) return;
    int s, d;
    if (e < E) { s = __ldg(&ei[e]); d = __ldg(&ei[E + e]); }
    else       { s = d = e - E; }
    int pos = atomicAdd(&cur[d], 1);
    csrc[pos] = s;
}

// ---------------- GEMM (3x bf16 mma.sync) + fused attention logits ----------
template <int M, bool BNIN, int H, int C>
__global__ __launch_bounds__(128, 6)
void gemm_attn_k(const float* __restrict__ A, const float4* __restrict__ wpack,
                 const float* __restrict__ bn,
                 const float* __restrict__ a_s, const float* __restrict__ a_d,
                 __nv_bfloat16* __restrict__ Cout, float* __restrict__ als,
                 float* __restrict__ ald, int rows) {
    const int NT8 = M / 8;
    const int NW  = NT8 / 2;
    const int LDA = 136;
    const int LD  = M + 4;

    __shared__ char smraw[17408];
    __nv_bfloat16* Ahi = (__nv_bfloat16*)smraw;
    __nv_bfloat16* Alo = Ahi + 32 * LDA;
    float* hs = (float*)smraw;

    int t = threadIdx.x;
    int w = t >> 5, lane = t & 31;
    int wr = w >> 1, wc = w & 1;
    int row0 = blockIdx.x * 32;

    for (int i = t; i < 32 * 32; i += 128) {
        int r = i >> 5, c4 = i & 31;
        float4 v = make_float4(0.f, 0.f, 0.f, 0.f);
        if (row0 + r < rows) {
            v = *(const float4*)&A[(size_t)(row0 + r) * 128 + c4 * 4];
            if (BNIN) {
                float4 sc = *(const float4*)&bn[2 * HD_ + c4 * 4];
                float4 sh = *(const float4*)&bn[3 * HD_ + c4 * 4];
                v.x = elu_f(v.x * sc.x + sh.x);
                v.y = elu_f(v.y * sc.y + sh.y);
                v.z = elu_f(v.z * sc.z + sh.z);
                v.w = elu_f(v.w * sc.w + sh.w);
            }
        }
        __nv_bfloat162 h0 = __float22bfloat162_rn(make_float2(v.x, v.y));
        __nv_bfloat162 h1 = __float22bfloat162_rn(make_float2(v.z, v.w));
        float2 f0 = __bfloat1622float2(h0);
        float2 f1 = __bfloat1622float2(h1);
        __nv_bfloat162 l0 = __float22bfloat162_rn(make_float2(v.x - f0.x, v.y - f0.y));
        __nv_bfloat162 l1 = __float22bfloat162_rn(make_float2(v.z - f1.x, v.w - f1.y));
        uint2 ph, pl;
        ph.x = *(unsigned*)&h0; ph.y = *(unsigned*)&h1;
        pl.x = *(unsigned*)&l0; pl.y = *(unsigned*)&l1;
        *(uint2*)&Ahi[r * LDA + c4 * 4] = ph;
        *(uint2*)&Alo[r * LDA + c4 * 4] = pl;
    }
    __syncthreads();

    float d[NW][4];
#pragma unroll
    for (int i = 0; i < NW; i++)
#pragma unroll
        for (int j = 0; j < 4; j++) d[i][j] = 0.f;

    int arow = wr * 16 + (lane & 15);
    int acolbase = (lane >> 4) << 3;
#pragma unroll
    for (int ks = 0; ks < 8; ks++) {
        unsigned a0, a1, a2, a3, q0, q1, q2, q3;
        unsigned hiaddr = smaddr(&Ahi[arow * LDA + ks * 16 + acolbase]);
        unsigned loaddr = smaddr(&Alo[arow * LDA + ks * 16 + acolbase]);
        LDMATRIX_X4(a0, a1, a2, a3, hiaddr);
        LDMATRIX_X4(q0, q1, q2, q3, loaddr);
        const float4* wp = wpack + (ks * NT8 + wc * NW) * 32 + lane;
#pragma unroll
        for (int i = 0; i < NW; i++) {
            float4 b = __ldg(&wp[i * 32]);
            unsigned bh0 = __float_as_uint(b.x), bh1 = __float_as_uint(b.y);
            unsigned bl0 = __float_as_uint(b.z), bl1 = __float_as_uint(b.w);
            MMA_BF16(d[i], a0, a1, a2, a3, bl0, bl1);
            MMA_BF16(d[i], q0, q1, q2, q3, bh0, bh1);
            MMA_BF16(d[i], a0, a1, a2, a3, bh0, bh1);
        }
    }
    __syncthreads();

    {
        int g = lane >> 2, c0 = lane & 3;
#pragma unroll
        for (int i = 0; i < NW; i++) {
            int n8 = wc * NW + i;
            int col = n8 * 8 + c0 * 2;
            *(float2*)&hs[(wr * 16 + g) * LD + col]     = make_float2(d[i][0], d[i][1]);
            *(float2*)&hs[(wr * 16 + g + 8) * LD + col] = make_float2(d[i][2], d[i][3]);
        }
    }
    __syncthreads();

    for (int i = t; i < 32 * (M / 4); i += 128) {
        int r = i / (M / 4), c4 = i % (M / 4);
        int gr = row0 + r;
        if (gr < rows) {
            float4 o = *(float4*)&hs[r * LD + c4 * 4];
            __nv_bfloat162 b0 = __float22bfloat162_rn(make_float2(o.x, o.y));
            __nv_bfloat162 b1 = __float22bfloat162_rn(make_float2(o.z, o.w));
            uint2 pk;
            pk.x = *(unsigned*)&b0;
            pk.y = *(unsigned*)&b1;
            *(uint2*)&Cout[(size_t)gr * M + c4 * 4] = pk;
        }
    }

    if (H == 4) {
        int row = t & 31, head = t >> 5;
        const float4* hrow = (const float4*)&hs[row * LD + head * C];
        const float4* ap = (const float4*)(a_s + head * C);
        const float4* dp = (const float4*)(a_d + head * C);
        float s1 = 0.f, s2 = 0.f;
#pragma unroll
        for (int c4 = 0; c4 < C / 4; c4++) {
            float4 v = hrow[c4];
            float4 a = __ldg(&ap[c4]);
            float4 dd = __ldg(&dp[c4]);
            s1 += v.x * a.x + v.y * a.y + v.z * a.z + v.w * a.w;
            s2 += v.x * dd.x + v.y * dd.y + v.z * dd.z + v.w * dd.w;
        }
        int gr = row0 + row;
        if (gr < rows) {
            als[gr * 4 + head] = s1;
            ald[gr * 4 + head] = s2;
        }
    } else if (t < 64) {
        int row = t & 31, sel = t >> 5;
        const float4* av = (const float4*)(sel ? a_d : a_s);
        const float4* hrow = (const float4*)&hs[row * LD];
        float acc1 = 0.f;
#pragma unroll
        for (int c4 = 0; c4 < C / 4; c4++) {
            float4 v = hrow[c4];
            float4 a = __ldg(&av[c4]);
            acc1 += v.x * a.x + v.y * a.y + v.z * a.z + v.w * a.w;
        }
        int gr = row0 + row;
        if (gr < rows) {
            if (sel) ald[gr] = acc1; else als[gr] = acc1;
        }
    }
}

__device__ __forceinline__ float4 bf4_to_f4(uint2 pk) {
    __nv_bfloat162 b0 = *(__nv_bfloat162*)&pk.x;
    __nv_bfloat162 b1 = *(__nv_bfloat162*)&pk.y;
    float2 f0 = __bfloat1622float2(b0);
    float2 f1 = __bfloat1622float2(b1);
    return make_float4(f0.x, f0.y, f1.x, f1.y);
}
__device__ __forceinline__ float2 bf2_to_f2(unsigned pk) {
    __nv_bfloat162 b = *(__nv_bfloat162*)&pk;
    return __bfloat1622float2(b);
}

// ---------------- fused per-node GAT aggregation (warp per node) ------------
template <int H, int M, bool STATS, bool POOL>
__global__ void aggregate_k(const int* __restrict__ roff, const int* __restrict__ csrc,
                            const __nv_bfloat16* __restrict__ h,
                            const float* __restrict__ als,
                            const float* __restrict__ ald, const float* __restrict__ bias,
                            float* __restrict__ out, float* __restrict__ bn,
                            const int* __restrict__ bid, float* __restrict__ pool,
                            float* __restrict__ cnt) {
    __shared__ float sred[2 * HD_];
    __shared__ float4 sE[8 * 32];
    __shared__ int    sS[8 * 32];
    int t = threadIdx.x;
    if (STATS) {
        if (t < 2 * HD_) sred[t] = 0.f;
        __syncthreads();
    }
    int node = (blockIdx.x * blockDim.x + t) >> 5;
    int lane = t & 31;
    int w = t >> 5;
    bool active = (node < NN);
    int beg = 0, end = 0;
    if (active) { beg = roff[node]; end = roff[node + 1]; }

    float ad0 = 0.f, ad1 = 0.f, ad2 = 0.f, ad3 = 0.f;
    if (active) {
        if (H == 4) {
            float4 tt = *(const float4*)&ald[node * 4];
            ad0 = tt.x; ad1 = tt.y; ad2 = tt.z; ad3 = tt.w;
        } else {
            ad0 = ald[node];
        }
    }

    int jj = beg + lane;
    bool have = active && (jj < end);
    int sreg = 0;
    float s0 = 0.f, s1 = 0.f, s2 = 0.f, s3 = 0.f;
    if (have) {
        sreg = csrc[jj];
        float4 e;
        if (H == 4) {
            float4 a = *(const float4*)&als[sreg * 4];
            e.x = __expf(lrelu(a.x + ad0));
            e.y = __expf(lrelu(a.y + ad1));
            e.z = __expf(lrelu(a.z + ad2));
            e.w = __expf(lrelu(a.w + ad3));
            s0 += e.x; s1 += e.y; s2 += e.z; s3 += e.w;
        } else {
            e.x = __expf(lrelu(als[sreg] + ad0));
            e.y = e.z = e.w = 0.f;
            s0 += e.x;
        }
        sE[w * 32 + lane] = e;
        sS[w * 32 + lane] = sreg;
    }
    for (int j = jj + 32; j < end; j += 32) {
        int s = csrc[j];
        if (H == 4) {
            float4 a = *(const float4*)&als[s * 4];
            s0 += __expf(lrelu(a.x + ad0));
            s1 += __expf(lrelu(a.y + ad1));
            s2 += __expf(lrelu(a.z + ad2));
            s3 += __expf(lrelu(a.w + ad3));
        } else {
            s0 += __expf(lrelu(als[s] + ad0));
        }
    }
#pragma unroll
    for (int o = 16; o; o >>= 1) {
        s0 += __shfl_xor_sync(0xffffffffu, s0, o);
        if (H == 4) {
            s1 += __shfl_xor_sync(0xffffffffu, s1, o);
            s2 += __shfl_xor_sync(0xffffffffu, s2, o);
            s3 += __shfl_xor_sync(0xffffffffu, s3, o);
        }
    }
    __syncwarp();

    int cnt_e = end - beg;
    int cached = cnt_e < 32 ? cnt_e : 32;

    if (H == 4) {
        float r0 = 1.f / (s0 + 1e-16f), r1 = 1.f / (s1 + 1e-16f);
        float r2 = 1.f / (s2 + 1e-16f), r3 = 1.f / (s3 + 1e-16f);
        int head = lane >> 3;
        float rv  = lane < 16 ? (lane < 8 ? r0 : r1) : (lane < 24 ? r2 : r3);
        float adh = lane < 16 ? (lane < 8 ? ad0 : ad1) : (lane < 24 ? ad2 : ad3);

        float4 acc = make_float4(0.f, 0.f, 0.f, 0.f);
        const float* eb = (const float*)&sE[w * 32];
        const int*   sb = &sS[w * 32];
        int j2 = 0;
        for (; j2 + 4 <= cached; j2 += 4) {
            int sA = sb[j2], sB = sb[j2 + 1], sC = sb[j2 + 2], sD = sb[j2 + 3];
            float evA = eb[(j2 + 0) * 4 + head];
            float evB = eb[(j2 + 1) * 4 + head];
            float evC = eb[(j2 + 2) * 4 + head];
            float evD = eb[(j2 + 3) * 4 + head];
            uint2 pA = *(const uint2*)&h[(size_t)sA * 128 + lane * 4];
            uint2 pB = *(const uint2*)&h[(size_t)sB * 128 + lane * 4];
            uint2 pC = *(const uint2*)&h[(size_t)sC * 128 + lane * 4];
            uint2 pD = *(const uint2*)&h[(size_t)sD * 128 + lane * 4];
            float4 hA = bf4_to_f4(pA), hB = bf4_to_f4(pB);
            float4 hC = bf4_to_f4(pC), hD = bf4_to_f4(pD);
            acc.x += hA.x * evA + hB.x * evB + hC.x * evC + hD.x * evD;
            acc.y += hA.y * evA + hB.y * evB + hC.y * evC + hD.y * evD;
            acc.z += hA.z * evA + hB.z * evB + hC.z * evC + hD.z * evD;
            acc.w += hA.w * evA + hB.w * evB + hC.w * evC + hD.w * evD;
        }
        for (; j2 < cached; j2++) {
            int sA = sb[j2];
            float evA = eb[j2 * 4 + head];
            float4 hA = bf4_to_f4(*(const uint2*)&h[(size_t)sA * 128 + lane * 4]);
            acc.x += hA.x * evA; acc.y += hA.y * evA;
            acc.z += hA.z * evA; acc.w += hA.w * evA;
        }
        for (int j = beg + 32; j < end; j++) {
            int s = csrc[j];
            float4 a = *(const float4*)&als[s * 4];
            float ah = lane < 16 ? (lane < 8 ? a.x : a.y) : (lane < 24 ? a.z : a.w);
            float ev = __expf(lrelu(ah + adh));
            float4 hv = bf4_to_f4(*(const uint2*)&h[(size_t)s * 128 + lane * 4]);
            acc.x += hv.x * ev; acc.y += hv.y * ev;
            acc.z += hv.z * ev; acc.w += hv.w * ev;
        }
        float4 bi = active ? *(const float4*)&bias[lane * 4]
                           : make_float4(0.f, 0.f, 0.f, 0.f);
        float4 ov;
        ov.x = acc.x * rv + bi.x;
        ov.y = acc.y * rv + bi.y;
        ov.z = acc.z * rv + bi.z;
        ov.w = acc.w * rv + bi.w;
        if (active) *(float4*)&out[(size_t)node * 128 + lane * 4] = ov;

        if (STATS) {
            if (active) {
                int ch = lane * 4;
                atomicAdd(&sred[ch + 0], ov.x);
                atomicAdd(&sred[ch + 1], ov.y);
                atomicAdd(&sred[ch + 2], ov.z);
                atomicAdd(&sred[ch + 3], ov.w);
                atomicAdd(&sred[HD_ + ch + 0], ov.x * ov.x);
                atomicAdd(&sred[HD_ + ch + 1], ov.y * ov.y);
                atomicAdd(&sred[HD_ + ch + 2], ov.z * ov.z);
                atomicAdd(&sred[HD_ + ch + 3], ov.w * ov.w);
            }
            __syncthreads();
            if (t < 2 * HD_) atomicAdd(&bn[t], sred[t]);
        }
    } else {
        float r0 = 1.f / (s0 + 1e-16f);
        float2 acc = make_float2(0.f, 0.f);
        const float* eb = (const float*)&sE[w * 32];
        const int*   sb = &sS[w * 32];
        int j2 = 0;
        for (; j2 + 4 <= cached; j2 += 4) {
            int sA = sb[j2], sB = sb[j2 + 1], sC = sb[j2 + 2], sD = sb[j2 + 3];
            float eA = eb[(j2 + 0) * 4];
            float eB = eb[(j2 + 1) * 4];
            float eC = eb[(j2 + 2) * 4];
            float eD = eb[(j2 + 3) * 4];
            float2 hA = bf2_to_f2(*(const unsigned*)&h[(size_t)sA * 64 + lane * 2]);
            float2 hB = bf2_to_f2(*(const unsigned*)&h[(size_t)sB * 64 + lane * 2]);
            float2 hC = bf2_to_f2(*(const unsigned*)&h[(size_t)sC * 64 + lane * 2]);
            float2 hD = bf2_to_f2(*(const unsigned*)&h[(size_t)sD * 64 + lane * 2]);
            acc.x += hA.x * eA + hB.x * eB + hC.x * eC + hD.x * eD;
            acc.y += hA.y * eA + hB.y * eB + hC.y * eC + hD.y * eD;
        }
        for (; j2 < cached; j2++) {
            int sA = sb[j2];
            float eA = eb[j2 * 4];
            float2 hA = bf2_to_f2(*(const unsigned*)&h[(size_t)sA * 64 + lane * 2]);
            acc.x += hA.x * eA;
            acc.y += hA.y * eA;
        }
        for (int j = beg + 32; j < end; j++) {
            int s = csrc[j];
            float ev = __expf(lrelu(als[s] + ad0));
            float2 hv = bf2_to_f2(*(const unsigned*)&h[(size_t)s * 64 + lane * 2]);
            acc.x += hv.x * ev;
            acc.y += hv.y * ev;
        }
        if (active) {
            float2 bi = *(const float2*)&bias[lane * 2];
            float2 ov;
            ov.x = acc.x * r0 + bi.x;
            ov.y = acc.y * r0 + bi.y;
            *(float2*)&out[(size_t)node * 64 + lane * 2] = ov;
            if (POOL) {
                int g = __ldg(&bid[node]);
                atomicAdd(&pool[g * OUTC + lane * 2],     ov.x);
                atomicAdd(&pool[g * OUTC + lane * 2 + 1], ov.y);
                if (lane == 0) atomicAdd(&cnt[g], 1.f);
            }
        }
    }
}

// ---------------- BN finalize ----------------
__global__ void bn_finalize(float* __restrict__ bn, const float* __restrict__ g,
                            const float* __restrict__ be, float* __restrict__ pool,
                            float* __restrict__ cnt, int clearPool) {
    int j = threadIdx.x;
    float mu = bn[j] / (float)NN;
    float var = bn[HD_ + j] / (float)NN - mu * mu;
    float sc = __ldg(&g[j]) * rsqrtf(var + 1e-5f);
    bn[2 * HD_ + j] = sc;
    bn[3 * HD_ + j] = __ldg(&be[j]) - mu * sc;
    bn[j] = 0.f;
    bn[HD_ + j] = 0.f;
    if (clearPool) {
        for (int i = j; i < NGRP * OUTC; i += HD_) pool[i] = 0.f;
        if (j < NGRP) cnt[j] = 0.f;
    }
}

__global__ void pool_fin(const float* __restrict__ pool, const float* __restrict__ cnt,
                         float* __restrict__ out) {
    int i = blockIdx.x * blockDim.x + threadIdx.x;
    if (i >= NGRP * OUTC) return;
    float c = cnt[i >> 6];
    out[i] = pool[i] / fmaxf(c, 1.f);
}

// ---------------- host ----------------
extern "C" void kernel_launch(void* const* d_in, const int* in_sizes, int n_in,
                              void* d_out, int out_size) {
    const float* x   = (const float*)d_in[0];
    const int*   ei  = (const int*)d_in[1];
    const int*   bid = (const int*)d_in[2];
    const float *W[4], *As[4], *Ad[4], *B[4];
    for (int i = 0; i < 4; i++) {
        W[i]  = (const float*)d_in[3 + 4 * i];
        As[i] = (const float*)d_in[4 + 4 * i];
        Ad[i] = (const float*)d_in[5 + 4 * i];
        B[i]  = (const float*)d_in[6 + 4 * i];
    }
    const float *G[3], *Be[3];
    for (int i = 0; i < 3; i++) {
        G[i]  = (const float*)d_in[19 + 2 * i];
        Be[i] = (const float*)d_in[20 + 2 * i];
    }
    int E  = in_sizes[1] / 2;
    int ET = E + NN;

    __nv_bfloat16* h_;
    float *agg_, *als_, *ald_, *bn_, *pool_, *cnt_;
    float4* wp_;
    int *deg_, *roff_, *cur_, *csrc_, *bsum_;
    cudaGetSymbolAddress((void**)&h_,    g_h);
    cudaGetSymbolAddress((void**)&agg_,  g_agg);
    cudaGetSymbolAddress((void**)&als_,  g_als);
    cudaGetSymbolAddress((void**)&ald_,  g_ald);
    cudaGetSymbolAddress((void**)&deg_,  g_deg);
    cudaGetSymbolAddress((void**)&roff_, g_roff);
    cudaGetSymbolAddress((void**)&cur_,  g_cur);
    cudaGetSymbolAddress((void**)&csrc_, g_csrc);
    cudaGetSymbolAddress((void**)&bsum_, g_bsum);
    cudaGetSymbolAddress((void**)&bn_,   g_bn);
    cudaGetSymbolAddress((void**)&pool_, g_pool);
    cudaGetSymbolAddress((void**)&cnt_,  g_cnt);
    cudaGetSymbolAddress((void**)&wp_,   g_wpack);

    const int TB = 256;
    const int AGG_BLOCKS = ceil_div(NN * 32, TB);
    const int GB = ceil_div(NN, 32);
    const int EB = ceil_div(ET, TB);

    // lazily-created side stream + fork/join events (host handles only; no
    // device allocations). Created once; reused across calls.
    static cudaStream_t s2 = nullptr;
    static cudaEvent_t evFork = nullptr, evJoin = nullptr;
    if (!s2) {
        cudaStreamCreateWithFlags(&s2, cudaStreamNonBlocking);
        cudaEventCreateWithFlags(&evFork, cudaEventDisableTiming);
        cudaEventCreateWithFlags(&evJoin, cudaEventDisableTiming);
    }

    // ---- fork: CSR chain on s2, overlapped with wpack + layer-0 GEMM ----
    cudaEventRecord(evFork, 0);
    cudaStreamWaitEvent(s2, evFork, 0);

    clear_i<<<128, TB, 0, s2>>>(deg_, NN);
    hist_k<<<EB, TB, 0, s2>>>(ei, deg_, E, ET);
    scan1_k<<<NBLK, SB, 0, s2>>>(deg_, bsum_);
    scan2_k<<<1, 256, 0, s2>>>(bsum_, roff_);
    scan3_k<<<NBLK, SB, 0, s2>>>(deg_, bsum_, roff_, cur_);
    scatter_k<<<EB, TB, 0, s2>>>(ei, cur_, csrc_, E, ET);
    cudaEventRecord(evJoin, s2);

    wpack_all<<<dim3(8, 16, 4), 32>>>(W[0], W[1], W[2], W[3], wp_);
    gemm_attn_k<128, false, 4, 32><<<GB, 128>>>(x, wp_, bn_, As[0], Ad[0],
                                                h_, als_, ald_, NN);

    cudaStreamWaitEvent(0, evJoin, 0);   // join before aggregation

    // ---- layer 0 aggregation ----
    aggregate_k<4, 128, true, false><<<AGG_BLOCKS, TB>>>(roff_, csrc_, h_, als_, ald_,
                                                         B[0], agg_, bn_, bid, pool_, cnt_);
    bn_finalize<<<1, HD_>>>(bn_, G[0], Be[0], pool_, cnt_, 0);

    // ---- layers 1,2 ----
    for (int l = 1; l < 3; l++) {
        gemm_attn_k<128, true, 4, 32><<<GB, 128>>>(agg_, wp_ + (size_t)l * 4096, bn_,
                                                   As[l], Ad[l], h_, als_, ald_, NN);
        aggregate_k<4, 128, true, false><<<AGG_BLOCKS, TB>>>(roff_, csrc_, h_, als_, ald_,
                                                             B[l], agg_, bn_, bid, pool_, cnt_);
        bn_finalize<<<1, HD_>>>(bn_, G[l], Be[l], pool_, cnt_, l == 2);
    }

    // ---- layer 3 (H=1, OUT=64) with fused pool accumulation ----
    gemm_attn_k<64, true, 1, 64><<<GB, 128>>>(agg_, wp_ + (size_t)3 * 4096, bn_,
                                              As[3], Ad[3], h_, als_, ald_, NN);
    aggregate_k<1, 64, false, true><<<AGG_BLOCKS, TB>>>(roff_, csrc_, h_, als_, ald_,
                                                        B[3], agg_, bn_, bid, pool_, cnt_);

    pool_fin<<<ceil_div(NGRP * OUTC, TB), TB>>>(pool_, cnt_, (float*)d_out);
}